// round 10
// baseline (speedup 1.0000x reference)
#include <cuda_runtime.h>
#include <math.h>
#include <stdint.h>

#define BB 2
#define TT 1024
#define CC 1024
#define HH 8
#define HD 128
#define LL 4
#define FFD 100
#define FFP 128
#define VV 32000
#define NTOK (BB*TT)
#define SCALE 0.08838834764831845f
#define LN_EPS 1e-5f

/* ---- attn (mma.sync) tiles ---- */
#define TMM 64
#define TNN 128
#define KC  32
#define BSTRIDE 136

/* ---- dense ldmatrix GEMM ---- */
#define GT  128          /* tile M = N = 128 */
#define GKT 32           /* K chunk */
#define STAGE_B 16384    /* bytes per operand stage: 128 rows x 128B */
#define GSMEM (4*STAGE_B)/* A0,A1,B0,B1 = 64KB */

// ---------------- scratch ----------------
__device__ float g_h [NTOK*CC];
__device__ float g_hn[NTOK*CC];
__device__ float g_q [NTOK*CC];
__device__ float g_k [NTOK*CC];
__device__ float g_v [NTOK*CC];
__device__ float g_o [NTOK*CC];
__device__ float g_ff[NTOK*FFP];

// ---------------- helpers ----------------
__device__ __forceinline__ uint32_t f2tf(float f) {
    uint32_t r; asm("cvt.rna.tf32.f32 %0, %1;" : "=r"(r) : "f"(f)); return r;
}
__device__ __forceinline__ uint32_t smem_u32(const void* p) {
    uint32_t a;
    asm("{ .reg .u64 t; cvta.to.shared.u64 t, %1; cvt.u32.u64 %0, t; }" : "=r"(a) : "l"(p));
    return a;
}
__device__ __forceinline__ void mma_tf32(float c[4], uint32_t a0, uint32_t a1,
                                         uint32_t a2, uint32_t a3,
                                         uint32_t b0, uint32_t b1) {
    asm("mma.sync.aligned.m16n8k8.row.col.f32.tf32.tf32.f32 "
        "{%0,%1,%2,%3}, {%4,%5,%6,%7}, {%8,%9}, {%0,%1,%2,%3};"
        : "+f"(c[0]), "+f"(c[1]), "+f"(c[2]), "+f"(c[3])
        : "r"(a0), "r"(a1), "r"(a2), "r"(a3), "r"(b0), "r"(b1));
}
__device__ __forceinline__ void ldsm4(uint32_t a[4], uint32_t addr) {
    asm volatile("ldmatrix.sync.aligned.m8n8.x4.shared.b16 {%0,%1,%2,%3}, [%4];"
                 : "=r"(a[0]), "=r"(a[1]), "=r"(a[2]), "=r"(a[3]) : "r"(addr));
}
__device__ __forceinline__ void ldsm2(uint32_t b[2], uint32_t addr) {
    asm volatile("ldmatrix.sync.aligned.m8n8.x2.shared.b16 {%0,%1}, [%2];"
                 : "=r"(b[0]), "=r"(b[1]) : "r"(addr));
}

// ================= dense GEMM: 128x128x32, 512 thr, 16 warps, ldmatrix =================
// A row-major (lda), B row-major [k][n] (ldb). grid = (M/128, ceil(N/128)).
template<bool RELU, bool ADD, bool NG, bool KG>
__global__ __launch_bounds__(512)
void gemm_lds(const float* __restrict__ A, int lda,
              const float* __restrict__ B, int ldb,
              const float* __restrict__ bias,
              const float* __restrict__ addp, int ldadd,
              float* __restrict__ C, int ldc,
              int N, int K)
{
    extern __shared__ uint32_t sm[];
    uint32_t smb = smem_u32(sm);
    int t = threadIdx.x, wid = t >> 5, lane = t & 31;
    int m0 = blockIdx.x * GT, n0 = blockIdx.y * GT;
    int warp_m = (wid & 3) * 32, warp_n = (wid >> 2) * 32;
    int nch = (K + GKT - 1) / GKT;

    // ---- fill mappings ----
    int ar = t >> 2;            // A row 0..127
    int aq = (t & 3) * 2;       // A first 16B-quad (0,2,4,6)
    int bn = t & 127;           // B n-row
    int bq = (t >> 2) & 0x7FFFFFFF;     // (unused)
    int bqq = (t >> 7) * 2;     // B first quad (0,2,4,6)
    bool bok = !NG || (n0 + bn) < N;
    const float* Ap = A + (size_t)(m0 + ar) * lda;

    const float4 z4 = make_float4(0.f, 0.f, 0.f, 0.f);
    float4 rA0, rA1;
    float  rB[8];

    // ldg chunk 0
    {
        int k = aq * 4;
        rA0 = (!KG || k     < K) ? *(const float4*)&Ap[k]     : z4;
        rA1 = (!KG || k + 4 < K) ? *(const float4*)&Ap[k + 4] : z4;
        #pragma unroll
        for (int j = 0; j < 8; j++) {
            int kk = bqq * 4 + j;
            rB[j] = (bok && (!KG || kk < K)) ? B[(size_t)kk * ldb + n0 + bn] : 0.f;
        }
    }

    // sts chunk 0 -> buf 0
    {
        uint32_t* pA = sm + ar * 32;
        *(uint4*)&pA[((aq     ^ (ar & 7)) << 2)] = make_uint4(f2tf(rA0.x), f2tf(rA0.y), f2tf(rA0.z), f2tf(rA0.w));
        *(uint4*)&pA[(((aq+1) ^ (ar & 7)) << 2)] = make_uint4(f2tf(rA1.x), f2tf(rA1.y), f2tf(rA1.z), f2tf(rA1.w));
        uint32_t* pB = sm + 2*(STAGE_B/4)*2/2*2;  // dummy (replaced below)
        pB = sm + (2*STAGE_B)/4 + bn * 32;
        *(uint4*)&pB[((bqq     ^ (bn & 7)) << 2)] = make_uint4(f2tf(rB[0]), f2tf(rB[1]), f2tf(rB[2]), f2tf(rB[3]));
        *(uint4*)&pB[(((bqq+1) ^ (bn & 7)) << 2)] = make_uint4(f2tf(rB[4]), f2tf(rB[5]), f2tf(rB[6]), f2tf(rB[7]));
    }
    __syncthreads();

    // ---- per-lane ldmatrix constants ----
    int l7 = lane & 7;
    int a_roff = ((lane >> 3) & 1) * 8 + l7;  // row offset within 16-row subtile
    int a_qhi  = lane >> 4;                   // quad select (0/1)
    int b_qhi  = (lane >> 3) & 1;
    // per-(warp) row bases (bytes, buffer 0); buffer 1 adds STAGE_B
    uint32_t pAr[2], pBr[4];
    #pragma unroll
    for (int ms = 0; ms < 2; ms++)
        pAr[ms] = smb + (warp_m + ms * 16 + a_roff) * 128;
    #pragma unroll
    for (int ns = 0; ns < 4; ns++)
        pBr[ns] = smb + 2 * STAGE_B + (warp_n + ns * 8 + l7) * 128;

    float acc[2][4][4] = {};

    for (int c = 0; c < nch; c++) {
        uint32_t boff = (c & 1) ? STAGE_B : 0;

        // prefetch next chunk
        if (c + 1 < nch) {
            int k0 = (c + 1) * GKT;
            int k = k0 + aq * 4;
            rA0 = (!KG || k     < K) ? *(const float4*)&Ap[k]     : z4;
            rA1 = (!KG || k + 4 < K) ? *(const float4*)&Ap[k + 4] : z4;
            #pragma unroll
            for (int j = 0; j < 8; j++) {
                int kk = k0 + bqq * 4 + j;
                rB[j] = (bok && (!KG || kk < K)) ? B[(size_t)kk * ldb + n0 + bn] : 0.f;
            }
        }

        // MMA over current buffer
        #pragma unroll
        for (int ks = 0; ks < 4; ks++) {
            uint32_t aswz = (uint32_t)(((2 * ks + a_qhi) ^ l7) << 4);
            uint32_t bswz = (uint32_t)(((2 * ks + b_qhi) ^ l7) << 4);
            uint32_t a[2][4], b[4][2];
            #pragma unroll
            for (int ms = 0; ms < 2; ms++) ldsm4(a[ms], pAr[ms] + boff + aswz);
            #pragma unroll
            for (int ns = 0; ns < 4; ns++) ldsm2(b[ns], pBr[ns] + boff + bswz);
            #pragma unroll
            for (int i = 0; i < 2; i++)
                #pragma unroll
                for (int j = 0; j < 4; j++)
                    mma_tf32(acc[i][j], a[i][0], a[i][1], a[i][2], a[i][3], b[j][0], b[j][1]);
        }

        // store next chunk into other buffer
        if (c + 1 < nch) {
            uint32_t nxt = ((c + 1) & 1) ? (STAGE_B / 4) : 0;
            uint32_t* pA = sm + nxt + ar * 32;
            *(uint4*)&pA[((aq     ^ (ar & 7)) << 2)] = make_uint4(f2tf(rA0.x), f2tf(rA0.y), f2tf(rA0.z), f2tf(rA0.w));
            *(uint4*)&pA[(((aq+1) ^ (ar & 7)) << 2)] = make_uint4(f2tf(rA1.x), f2tf(rA1.y), f2tf(rA1.z), f2tf(rA1.w));
            uint32_t* pB = sm + (2 * STAGE_B) / 4 + nxt + bn * 32;
            *(uint4*)&pB[((bqq     ^ (bn & 7)) << 2)] = make_uint4(f2tf(rB[0]), f2tf(rB[1]), f2tf(rB[2]), f2tf(rB[3]));
            *(uint4*)&pB[(((bqq+1) ^ (bn & 7)) << 2)] = make_uint4(f2tf(rB[4]), f2tf(rB[5]), f2tf(rB[6]), f2tf(rB[7]));
        }
        __syncthreads();
    }

    // ---- epilogue ----
    int lr = lane >> 2, lc = lane & 3;
    #pragma unroll
    for (int i = 0; i < 2; i++) {
        int r0 = m0 + warp_m + i * 16 + lr;
        #pragma unroll
        for (int j = 0; j < 4; j++) {
            int cg = n0 + warp_n + j * 8 + 2 * lc;
            if (NG && cg >= N) continue;
            float2 bb = *(const float2*)&bias[cg];
            float v0 = acc[i][j][0] + bb.x, v1 = acc[i][j][1] + bb.y;
            float v2 = acc[i][j][2] + bb.x, v3 = acc[i][j][3] + bb.y;
            if (ADD) {
                float2 p0 = *(const float2*)&addp[(size_t)r0*ldadd + cg];
                float2 p1 = *(const float2*)&addp[(size_t)(r0+8)*ldadd + cg];
                v0 += p0.x; v1 += p0.y; v2 += p1.x; v3 += p1.y;
            }
            if (RELU) {
                v0 = fmaxf(v0,0.f); v1 = fmaxf(v1,0.f);
                v2 = fmaxf(v2,0.f); v3 = fmaxf(v3,0.f);
            }
            *(float2*)&C[(size_t)r0*ldc + cg]     = make_float2(v0, v1);
            *(float2*)&C[(size_t)(r0+8)*ldc + cg] = make_float2(v2, v3);
        }
    }
}

// ================= attention path (mma.sync tf32) =================
template<int ROWS, bool KG>
__device__ __forceinline__ void ldg_rs(float4* reg, const float* __restrict__ src,
                                       int ld, int kb, int K)
{
    int t = threadIdx.x;
    #pragma unroll
    for (int i = 0; i < ROWS/32; i++) {
        int m = i*32 + (t >> 3);
        int k = kb + (t & 7)*4;
        if (!KG || k < K) reg[i] = *(const float4*)&src[(size_t)m*ld + k];
        else              reg[i] = make_float4(0.f,0.f,0.f,0.f);
    }
}
template<int ROWS>
__device__ __forceinline__ void sts_rs(uint32_t* smp, const float4* reg)
{
    int t = threadIdx.x;
    #pragma unroll
    for (int i = 0; i < ROWS/32; i++) {
        int m = i*32 + (t >> 3);
        int k4 = t & 7;
        uint32_t* p = &smp[m*32 + ((k4 ^ (m & 7)) << 2)];
        p[0] = f2tf(reg[i].x); p[1] = f2tf(reg[i].y);
        p[2] = f2tf(reg[i].z); p[3] = f2tf(reg[i].w);
    }
}
template<bool NG, bool KG>
__device__ __forceinline__ void ldg_kn(float4* reg, const float* __restrict__ src,
                                       int ldb, int kb, int n0, int N, int K)
{
    int t = threadIdx.x;
    #pragma unroll
    for (int i = 0; i < 4; i++) {
        int r = i*8 + (t >> 5);
        int c = (t & 31)*4;
        bool ok = (!KG || (kb + r) < K) && (!NG || (n0 + c) < N);
        if (ok) reg[i] = *(const float4*)&src[(size_t)(kb+r)*ldb + n0 + c];
        else    reg[i] = make_float4(0.f,0.f,0.f,0.f);
    }
}
__device__ __forceinline__ void sts_kn(uint32_t* smp, const float4* reg)
{
    int t = threadIdx.x;
    #pragma unroll
    for (int i = 0; i < 4; i++) {
        int r = i*8 + (t >> 5);
        int c = (t & 31)*4;
        uint32_t* p = &smp[r*BSTRIDE + c];
        p[0] = f2tf(reg[i].x); p[1] = f2tf(reg[i].y);
        p[2] = f2tf(reg[i].z); p[3] = f2tf(reg[i].w);
    }
}
__device__ __forceinline__ void mma_chunk_kn(const uint32_t* smA, const uint32_t* smB,
                                             float acc[2][4][4],
                                             int warp_m, int warp_n, int lr, int lc)
{
    #pragma unroll
    for (int ks = 0; ks < 4; ks++) {
        int kb = ks*8, kb4 = ks*2;
        int swz = ((kb4 ^ lr) << 2) + lc;
        uint32_t b[4][2];
        #pragma unroll
        for (int j = 0; j < 4; j++) {
            int n = warp_n + j*8 + lr;
            b[j][0] = smB[(kb + lc)*BSTRIDE + n];
            b[j][1] = smB[(kb + 4 + lc)*BSTRIDE + n];
        }
        #pragma unroll
        for (int i = 0; i < 2; i++) {
            int mb = warp_m + i*16;
            uint32_t a0 = smA[(mb + lr)*32 + swz];
            uint32_t a1 = smA[(mb + 8 + lr)*32 + swz];
            uint32_t a2 = smA[(mb + lr)*32 + (swz ^ 4)];
            uint32_t a3 = smA[(mb + 8 + lr)*32 + (swz ^ 4)];
            #pragma unroll
            for (int j = 0; j < 4; j++)
                mma_tf32(acc[i][j], a0, a1, a2, a3, b[j][0], b[j][1]);
        }
    }
}
__device__ __forceinline__ void mma_chunk_rs(const uint32_t* smA, const uint32_t* smB,
                                             float acc[2][4][4],
                                             int warp_m, int warp_n, int lr, int lc)
{
    #pragma unroll
    for (int ks = 0; ks < 4; ks++) {
        int kb4 = ks*2;
        int swz = ((kb4 ^ lr) << 2) + lc;
        uint32_t b[4][2];
        #pragma unroll
        for (int j = 0; j < 4; j++) {
            int n = warp_n + j*8 + lr;
            b[j][0] = smB[n*32 + swz];
            b[j][1] = smB[n*32 + (swz ^ 4)];
        }
        #pragma unroll
        for (int i = 0; i < 2; i++) {
            int mb = warp_m + i*16;
            uint32_t a0 = smA[(mb + lr)*32 + swz];
            uint32_t a1 = smA[(mb + 8 + lr)*32 + swz];
            uint32_t a2 = smA[(mb + lr)*32 + (swz ^ 4)];
            uint32_t a3 = smA[(mb + 8 + lr)*32 + (swz ^ 4)];
            #pragma unroll
            for (int j = 0; j < 4; j++)
                mma_tf32(acc[i][j], a0, a1, a2, a3, b[j][0], b[j][1]);
        }
    }
}

__global__ __launch_bounds__(256)
void scores_tc(const float* __restrict__ Q, const float* __restrict__ Kc,
               float* __restrict__ attn)
{
    int zb = blockIdx.z, b = zb >> 3, h = zb & 7;
    int m0 = blockIdx.y * TMM, n0 = blockIdx.x * TNN;
    int t = threadIdx.x;
    float* S = attn + (size_t)zb*TT*TT;

    if (n0 > m0 + (TMM-1)) {
        int base = t*4;
        #pragma unroll
        for (int it = 0; it < 8; it++) {
            int e = base + it*1024;
            int r = e >> 7, cidx = e & 127;
            *(float4*)&S[(size_t)(m0+r)*TT + n0 + cidx] = make_float4(0.f,0.f,0.f,0.f);
        }
        return;
    }

    __shared__ uint32_t smA[TMM*32];
    __shared__ uint32_t smB[TNN*32];
    int wid = t >> 5, lane = t & 31;
    int lr = lane >> 2, lc = lane & 3;
    int warp_m = (wid & 1)*32, warp_n = (wid >> 1)*32;

    const float* Aq = Q  + (size_t)b*TT*CC + h*HD + (size_t)m0*CC;
    const float* Ak = Kc + (size_t)b*TT*CC + h*HD + (size_t)n0*CC;

    float acc[2][4][4] = {};
    float4 rA[2], rB[4];
    ldg_rs<TMM,false>(rA, Aq, CC, 0, HD);
    ldg_rs<TNN,false>(rB, Ak, CC, 0, HD);

    #pragma unroll
    for (int c = 0; c < HD/KC; c++) {
        sts_rs<TMM>(smA, rA);
        sts_rs<TNN>(smB, rB);
        __syncthreads();
        if (c + 1 < HD/KC) {
            ldg_rs<TMM,false>(rA, Aq, CC, (c+1)*KC, HD);
            ldg_rs<TNN,false>(rB, Ak, CC, (c+1)*KC, HD);
        }
        mma_chunk_rs(smA, smB, acc, warp_m, warp_n, lr, lc);
        __syncthreads();
    }

    float slope = exp2f(-(float)(h+1));
    #pragma unroll
    for (int i = 0; i < 2; i++) {
        int r0 = m0 + warp_m + i*16 + lr;
        #pragma unroll
        for (int j = 0; j < 4; j++) {
            int cg = n0 + warp_n + j*8 + 2*lc;
            float v0 = (cg   <= r0  ) ? acc[i][j][0]*SCALE + slope*(float)(cg  -r0  ) : 0.f;
            float v1 = (cg+1 <= r0  ) ? acc[i][j][1]*SCALE + slope*(float)(cg+1-r0  ) : 0.f;
            float v2 = (cg   <= r0+8) ? acc[i][j][2]*SCALE + slope*(float)(cg  -r0-8) : 0.f;
            float v3 = (cg+1 <= r0+8) ? acc[i][j][3]*SCALE + slope*(float)(cg+1-r0-8) : 0.f;
            *(float2*)&S[(size_t)r0*TT + cg]     = make_float2(v0, v1);
            *(float2*)&S[(size_t)(r0+8)*TT + cg] = make_float2(v2, v3);
        }
    }
}

__global__ void softmax_kernel(float* __restrict__ attnL)
{
    int rowid = blockIdx.x;
    int i = rowid & (TT-1);
    int L = i + 1;
    float* r = attnL + (size_t)rowid * TT;
    __shared__ float red[256];
    int tid = threadIdx.x;

    float m = -INFINITY;
    for (int c = tid; c < L; c += 256) m = fmaxf(m, r[c]);
    red[tid] = m; __syncthreads();
    for (int q = 128; q > 0; q >>= 1) { if (tid < q) red[tid] = fmaxf(red[tid], red[tid+q]); __syncthreads(); }
    m = red[0]; __syncthreads();

    float s = 0.f;
    for (int c = tid; c < L; c += 256) { float e = __expf(r[c]-m); r[c] = e; s += e; }
    red[tid] = s; __syncthreads();
    for (int q = 128; q > 0; q >>= 1) { if (tid < q) red[tid] += red[tid+q]; __syncthreads(); }
    float inv = 1.f / red[0];

    for (int c = tid; c < L; c += 256) r[c] *= inv;
}

__global__ __launch_bounds__(256)
void av_tc(const float* __restrict__ attn, const float* __restrict__ V,
           float* __restrict__ O)
{
    int zb = blockIdx.z, b = zb >> 3, h = zb & 7;
    int m0 = blockIdx.y * TMM;
    int t = threadIdx.x, wid = t >> 5, lane = t & 31;
    int lr = lane >> 2, lc = lane & 3;
    int warp_m = (wid & 1)*32, warp_n = (wid >> 1)*32;

    const float* A  = attn + (size_t)zb*TT*TT + (size_t)m0*TT;
    const float* Bv = V + (size_t)b*TT*CC + h*HD;
    float*       Co = O + (size_t)b*TT*CC + h*HD;

    __shared__ uint32_t smA[TMM*32];
    __shared__ uint32_t smB[KC*BSTRIDE];

    float acc[2][4][4] = {};
    float4 rA[2], rB[4];
    int nch = (m0 + TMM)/KC;

    ldg_rs<TMM,false>(rA, A, TT, 0, TT);
    ldg_kn<false,false>(rB, Bv, CC, 0, 0, HD, TT);

    for (int c = 0; c < nch; c++) {
        sts_rs<TMM>(smA, rA);
        sts_kn(smB, rB);
        __syncthreads();
        if (c + 1 < nch) {
            ldg_rs<TMM,false>(rA, A, TT, (c+1)*KC, TT);
            ldg_kn<false,false>(rB, Bv, CC, (c+1)*KC, 0, HD, TT);
        }
        mma_chunk_kn(smA, smB, acc, warp_m, warp_n, lr, lc);
        __syncthreads();
    }

    #pragma unroll
    for (int i = 0; i < 2; i++) {
        int r0 = m0 + warp_m + i*16 + lr;
        #pragma unroll
        for (int j = 0; j < 4; j++) {
            int cg = warp_n + j*8 + 2*lc;
            *(float2*)&Co[(size_t)r0*CC + cg]     = make_float2(acc[i][j][0], acc[i][j][1]);
            *(float2*)&Co[(size_t)(r0+8)*CC + cg] = make_float2(acc[i][j][2], acc[i][j][3]);
        }
    }
}

// ---------------- embedding / layernorm ----------------
__global__ void embed_kernel(const int* __restrict__ x, const float* __restrict__ emb,
                             float* __restrict__ h)
{
    int idx = blockIdx.x * 256 + threadIdx.x;
    int n = idx >> 8, c = idx & 255;
    ((float4*)h)[idx] = ((const float4*)emb)[(size_t)x[n]*(CC/4) + c];
}

__global__ void ln_kernel(const float* __restrict__ in, const float* __restrict__ g,
                          const float* __restrict__ b, float* __restrict__ out)
{
    int row = blockIdx.x, tid = threadIdx.x;
    const float4* xr = (const float4*)(in + (size_t)row*CC);
    float4 x = xr[tid];
    __shared__ float red[32];

    float s = x.x + x.y + x.z + x.w;
    #pragma unroll
    for (int o = 16; o; o >>= 1) s += __shfl_xor_sync(0xffffffffu, s, o);
    if ((tid & 31) == 0) red[tid >> 5] = s;
    __syncthreads();
    if (tid == 0) {
        float tsum = 0.f;
        #pragma unroll
        for (int w = 0; w < 8; w++) tsum += red[w];
        red[0] = tsum;
    }
    __syncthreads();
    float mu = red[0] * (1.f/CC);
    __syncthreads();

    float4 d = make_float4(x.x-mu, x.y-mu, x.z-mu, x.w-mu);
    float v = d.x*d.x + d.y*d.y + d.z*d.z + d.w*d.w;
    #pragma unroll
    for (int o = 16; o; o >>= 1) v += __shfl_xor_sync(0xffffffffu, v, o);
    if ((tid & 31) == 0) red[tid >> 5] = v;
    __syncthreads();
    if (tid == 0) {
        float tsum = 0.f;
        #pragma unroll
        for (int w = 0; w < 8; w++) tsum += red[w];
        red[0] = tsum;
    }
    __syncthreads();
    float rstd = rsqrtf(red[0] * (1.f/CC) + LN_EPS);

    float4 gg = ((const float4*)g)[tid];
    float4 bb = ((const float4*)b)[tid];
    float4 o4;
    o4.x = d.x*rstd*gg.x + bb.x;
    o4.y = d.y*rstd*gg.y + bb.y;
    o4.z = d.z*rstd*gg.z + bb.z;
    o4.w = d.w*rstd*gg.w + bb.w;
    ((float4*)(out + (size_t)row*CC))[tid] = o4;
}

// ---------------- host ----------------
extern "C" void kernel_launch(void* const* d_in, const int* in_sizes, int n_in,
                              void* d_out, int out_size)
{
    const int*   x    = (const int*)  d_in[0];
    const float* emb  = (const float*)d_in[1];
    const float* Wq   = (const float*)d_in[2];
    const float* bq   = (const float*)d_in[3];
    const float* Wk   = (const float*)d_in[4];
    const float* bk   = (const float*)d_in[5];
    const float* Wv   = (const float*)d_in[6];
    const float* bv   = (const float*)d_in[7];
    const float* Wo   = (const float*)d_in[8];
    const float* bo   = (const float*)d_in[9];
    const float* W1   = (const float*)d_in[10];
    const float* b1   = (const float*)d_in[11];
    const float* W2   = (const float*)d_in[12];
    const float* b2   = (const float*)d_in[13];
    const float* ln1g = (const float*)d_in[14];
    const float* ln1b = (const float*)d_in[15];
    const float* ln3g = (const float*)d_in[16];
    const float* ln3b = (const float*)d_in[17];
    const float* lnfg = (const float*)d_in[18];
    const float* lnfb = (const float*)d_in[19];
    const float* Wout = (const float*)d_in[20];
    const float* bout = (const float*)d_in[21];

    float* out_logits = (float*)d_out;                   // [B,T,V]
    float* out_attn   = out_logits + (size_t)BB*TT*VV;   // [L,B,H,T,T]

    float *h, *hn, *q, *k, *v, *o, *ff;
    cudaGetSymbolAddress((void**)&h,  g_h);
    cudaGetSymbolAddress((void**)&hn, g_hn);
    cudaGetSymbolAddress((void**)&q,  g_q);
    cudaGetSymbolAddress((void**)&k,  g_k);
    cudaGetSymbolAddress((void**)&v,  g_v);
    cudaGetSymbolAddress((void**)&o,  g_o);
    cudaGetSymbolAddress((void**)&ff, g_ff);

    cudaFuncSetAttribute(gemm_lds<false,false,false,false>, cudaFuncAttributeMaxDynamicSharedMemorySize, GSMEM);
    cudaFuncSetAttribute(gemm_lds<false,true,false,false>,  cudaFuncAttributeMaxDynamicSharedMemorySize, GSMEM);
    cudaFuncSetAttribute(gemm_lds<true,false,true,false>,   cudaFuncAttributeMaxDynamicSharedMemorySize, GSMEM);
    cudaFuncSetAttribute(gemm_lds<false,true,false,true>,   cudaFuncAttributeMaxDynamicSharedMemorySize, GSMEM);

    embed_kernel<<<NTOK, 256>>>(x, emb, h);

    dim3 thrG(512), thr(256);
    dim3 gC(NTOK/GT, CC/GT);            // 16 x 8
    dim3 gS(TT/TNN, TT/TMM, BB*HH);
    dim3 gAV(1, TT/TMM, BB*HH);
    dim3 gF1(NTOK/GT, 1);
    dim3 gL(NTOK/GT, VV/GT);            // 16 x 250

    for (int l = 0; l < LL; l++) {
        float* attnL = out_attn + (size_t)l*BB*HH*TT*TT;

        ln_kernel<<<NTOK, 256>>>(h, ln1g + l*CC, ln1b + l*CC, hn);

        gemm_lds<false,false,false,false><<<gC, thrG, GSMEM>>>(hn, CC, Wq + (size_t)l*CC*CC, CC,
                                                               bq + l*CC, nullptr, 0, q, CC, CC, CC);
        gemm_lds<false,false,false,false><<<gC, thrG, GSMEM>>>(hn, CC, Wk + (size_t)l*CC*CC, CC,
                                                               bk + l*CC, nullptr, 0, k, CC, CC, CC);
        gemm_lds<false,false,false,false><<<gC, thrG, GSMEM>>>(hn, CC, Wv + (size_t)l*CC*CC, CC,
                                                               bv + l*CC, nullptr, 0, v, CC, CC, CC);

        scores_tc<<<gS, thr>>>(q, k, attnL);
        softmax_kernel<<<BB*HH*TT, 256>>>(attnL);
        av_tc<<<gAV, thr>>>(attnL, v, o);

        gemm_lds<false,true,false,false><<<gC, thrG, GSMEM>>>(o, CC, Wo + (size_t)l*CC*CC, CC,
                                                              bo + l*CC, h, CC, h, CC, CC, CC);

        ln_kernel<<<NTOK, 256>>>(h, ln3g + l*CC, ln3b + l*CC, hn);

        gemm_lds<true,false,true,false><<<gF1, thrG, GSMEM>>>(hn, CC, W1 + (size_t)l*CC*FFD, FFD,
                                                              b1 + l*FFD, nullptr, 0, ff, FFP, FFD, CC);
        gemm_lds<false,true,false,true><<<gC, thrG, GSMEM>>>(ff, FFP, W2 + (size_t)l*FFD*CC, CC,
                                                             b2 + l*CC, h, CC, h, CC, CC, FFD);
    }

    ln_kernel<<<NTOK, 256>>>(h, lnfg, lnfb, hn);
    gemm_lds<false,false,false,false><<<gL, thrG, GSMEM>>>(hn, CC, Wout, VV,
                                                           bout, nullptr, 0, out_logits, VV, VV, CC);
}

// round 11
// speedup vs baseline: 1.3025x; 1.3025x over previous
#include <cuda_runtime.h>
#include <cuda_fp16.h>
#include <math.h>
#include <stdint.h>

#define BB 2
#define TT 1024
#define CC 1024
#define HH 8
#define HD 128
#define LL 4
#define FFD 100
#define FFP 128
#define VV 32000
#define NTOK (BB*TT)
#define SCALE 0.08838834764831845f
#define LN_EPS 1e-5f

/* ---- attn (mma.sync tf32) tiles ---- */
#define TMM 64
#define TNN 128
#define KC  32
#define BSTRIDE 136

/* ---- fp16 dense gemm ---- */
#define GT   128         /* tile M = N */
#define HKC  32          /* K chunk */
#define HROW 20          /* half2 units per row: 16 data + 4 pad = 80B */
#define HSTAGE (128*HROW)/* uint32 units per operand stage */

// ---------------- scratch ----------------
__device__ float g_h [NTOK*CC];
__device__ float g_hn[NTOK*CC];
__device__ float g_q [NTOK*CC];
__device__ float g_k [NTOK*CC];
__device__ float g_v [NTOK*CC];
__device__ float g_o [NTOK*CC];
__device__ float g_ff[NTOK*FFP];

// ---------------- helpers ----------------
__device__ __forceinline__ uint32_t f2tf(float f) {
    uint32_t r; asm("cvt.rna.tf32.f32 %0, %1;" : "=r"(r) : "f"(f)); return r;
}
__device__ __forceinline__ uint32_t f2h2(float x, float y) {
    __half2 h = __floats2half2_rn(x, y);
    return *(uint32_t*)&h;
}
__device__ __forceinline__ void mma_tf32(float c[4], uint32_t a0, uint32_t a1,
                                         uint32_t a2, uint32_t a3,
                                         uint32_t b0, uint32_t b1) {
    asm("mma.sync.aligned.m16n8k8.row.col.f32.tf32.tf32.f32 "
        "{%0,%1,%2,%3}, {%4,%5,%6,%7}, {%8,%9}, {%0,%1,%2,%3};"
        : "+f"(c[0]), "+f"(c[1]), "+f"(c[2]), "+f"(c[3])
        : "r"(a0), "r"(a1), "r"(a2), "r"(a3), "r"(b0), "r"(b1));
}
__device__ __forceinline__ void mma_f16(float c[4], const uint32_t a[4], const uint32_t b[2]) {
    asm("mma.sync.aligned.m16n8k16.row.col.f32.f16.f16.f32 "
        "{%0,%1,%2,%3}, {%4,%5,%6,%7}, {%8,%9}, {%0,%1,%2,%3};"
        : "+f"(c[0]), "+f"(c[1]), "+f"(c[2]), "+f"(c[3])
        : "r"(a[0]), "r"(a[1]), "r"(a[2]), "r"(a[3]), "r"(b[0]), "r"(b[1]));
}

// ================= fp16 dense GEMM: 128x128x32, 256 thr, warp tile 64x32 =================
// A row-major (lda), B row-major [k][n] (ldb). grid = (M/128, ceil(N/128)).
template<bool RELU, bool ADD, bool NG, bool KG>
__global__ __launch_bounds__(256)
void gemm_h(const float* __restrict__ A, int lda,
            const float* __restrict__ B, int ldb,
            const float* __restrict__ bias,
            const float* __restrict__ addp, int ldadd,
            float* __restrict__ C, int ldc,
            int N, int K)
{
    __shared__ __align__(16) uint32_t smA[2*HSTAGE];
    __shared__ __align__(16) uint32_t smB[2*HSTAGE];
    int t = threadIdx.x, wid = t >> 5, lane = t & 31;
    int lr = lane >> 2, lc = lane & 3;
    int warp_m = (wid & 1) * 64, warp_n = (wid >> 1) * 32;
    int m0 = blockIdx.x * GT, n0 = blockIdx.y * GT;
    int nch = (K + HKC - 1) / HKC;

    // fill mappings
    int ar = t >> 1, akb = (t & 1) * 16;   // A: row, k base (16 floats)
    int bn = t & 127, bkb = (t >> 7) * 16; // B: n row, k base (16 floats)
    const float* Ap = A + (size_t)(m0 + ar) * lda;
    bool bok = !NG || (n0 + bn) < N;
    const float4 z4 = make_float4(0.f, 0.f, 0.f, 0.f);

    float4 rA[4];
    float  rB[16];

    // ---- load chunk 0 ----
    #pragma unroll
    for (int i = 0; i < 4; i++) {
        int k = akb + i * 4;
        rA[i] = (!KG || k < K) ? *(const float4*)&Ap[k] : z4;
    }
    #pragma unroll
    for (int j = 0; j < 16; j++) {
        int k = bkb + j;
        rB[j] = (bok && (!KG || k < K)) ? B[(size_t)k * ldb + n0 + bn] : 0.f;
    }

    // ---- store chunk 0 -> buf 0 ----
    {
        uint32_t* pA = smA + ar * HROW + (akb >> 1);
        uint4 h0 = make_uint4(f2h2(rA[0].x, rA[0].y), f2h2(rA[0].z, rA[0].w),
                              f2h2(rA[1].x, rA[1].y), f2h2(rA[1].z, rA[1].w));
        uint4 h1 = make_uint4(f2h2(rA[2].x, rA[2].y), f2h2(rA[2].z, rA[2].w),
                              f2h2(rA[3].x, rA[3].y), f2h2(rA[3].z, rA[3].w));
        *(uint4*)&pA[0] = h0; *(uint4*)&pA[4] = h1;
        uint32_t* pB = smB + bn * HROW + (bkb >> 1);
        uint4 g0 = make_uint4(f2h2(rB[0], rB[1]),  f2h2(rB[2], rB[3]),
                              f2h2(rB[4], rB[5]),  f2h2(rB[6], rB[7]));
        uint4 g1 = make_uint4(f2h2(rB[8], rB[9]),  f2h2(rB[10], rB[11]),
                              f2h2(rB[12], rB[13]),f2h2(rB[14], rB[15]));
        *(uint4*)&pB[0] = g0; *(uint4*)&pB[4] = g1;
    }
    __syncthreads();

    float acc[4][4][4] = {};

    for (int c = 0; c < nch; c++) {
        uint32_t cur = (c & 1) ? HSTAGE : 0;

        // prefetch next chunk into regs
        if (c + 1 < nch) {
            int k0 = (c + 1) * HKC;
            #pragma unroll
            for (int i = 0; i < 4; i++) {
                int k = k0 + akb + i * 4;
                rA[i] = (!KG || k < K) ? *(const float4*)&Ap[k] : z4;
            }
            #pragma unroll
            for (int j = 0; j < 16; j++) {
                int k = k0 + bkb + j;
                rB[j] = (bok && (!KG || k < K)) ? B[(size_t)k * ldb + n0 + bn] : 0.f;
            }
        }

        // ---- MMA over current buffer: 2 k16 steps ----
        const uint32_t* sA = smA + cur;
        const uint32_t* sB = smB + cur;
        #pragma unroll
        for (int ks = 0; ks < 2; ks++) {
            int ko = ks * 8 + lc;
            uint32_t b[4][2];
            #pragma unroll
            for (int j = 0; j < 4; j++) {
                int nb = (warp_n + j * 8 + lr) * HROW;
                b[j][0] = sB[nb + ko];
                b[j][1] = sB[nb + ko + 4];
            }
            #pragma unroll
            for (int i = 0; i < 4; i++) {
                int mb = (warp_m + i * 16 + lr) * HROW;
                uint32_t a[4];
                a[0] = sA[mb + ko];
                a[1] = sA[mb + 8 * HROW + ko];
                a[2] = sA[mb + ko + 4];
                a[3] = sA[mb + 8 * HROW + ko + 4];
                #pragma unroll
                for (int j = 0; j < 4; j++)
                    mma_f16(acc[i][j], a, b[j]);
            }
        }

        // store next chunk to other buffer
        if (c + 1 < nch) {
            uint32_t nxt = ((c + 1) & 1) ? HSTAGE : 0;
            uint32_t* pA = smA + nxt + ar * HROW + (akb >> 1);
            uint4 h0 = make_uint4(f2h2(rA[0].x, rA[0].y), f2h2(rA[0].z, rA[0].w),
                                  f2h2(rA[1].x, rA[1].y), f2h2(rA[1].z, rA[1].w));
            uint4 h1 = make_uint4(f2h2(rA[2].x, rA[2].y), f2h2(rA[2].z, rA[2].w),
                                  f2h2(rA[3].x, rA[3].y), f2h2(rA[3].z, rA[3].w));
            *(uint4*)&pA[0] = h0; *(uint4*)&pA[4] = h1;
            uint32_t* pB = smB + nxt + bn * HROW + (bkb >> 1);
            uint4 g0 = make_uint4(f2h2(rB[0], rB[1]),  f2h2(rB[2], rB[3]),
                                  f2h2(rB[4], rB[5]),  f2h2(rB[6], rB[7]));
            uint4 g1 = make_uint4(f2h2(rB[8], rB[9]),  f2h2(rB[10], rB[11]),
                                  f2h2(rB[12], rB[13]),f2h2(rB[14], rB[15]));
            *(uint4*)&pB[0] = g0; *(uint4*)&pB[4] = g1;
        }
        __syncthreads();
    }

    // ---- epilogue ----
    #pragma unroll
    for (int i = 0; i < 4; i++) {
        int r0 = m0 + warp_m + i * 16 + lr;
        #pragma unroll
        for (int j = 0; j < 4; j++) {
            int cg = n0 + warp_n + j * 8 + 2 * lc;
            if (NG && cg >= N) continue;
            float2 bb = *(const float2*)&bias[cg];
            float v0 = acc[i][j][0] + bb.x, v1 = acc[i][j][1] + bb.y;
            float v2 = acc[i][j][2] + bb.x, v3 = acc[i][j][3] + bb.y;
            if (ADD) {
                float2 p0 = *(const float2*)&addp[(size_t)r0*ldadd + cg];
                float2 p1 = *(const float2*)&addp[(size_t)(r0+8)*ldadd + cg];
                v0 += p0.x; v1 += p0.y; v2 += p1.x; v3 += p1.y;
            }
            if (RELU) {
                v0 = fmaxf(v0,0.f); v1 = fmaxf(v1,0.f);
                v2 = fmaxf(v2,0.f); v3 = fmaxf(v3,0.f);
            }
            *(float2*)&C[(size_t)r0*ldc + cg]     = make_float2(v0, v1);
            *(float2*)&C[(size_t)(r0+8)*ldc + cg] = make_float2(v2, v3);
        }
    }
}

// ================= attention path (mma.sync tf32) — proven =================
template<int ROWS, bool KG>
__device__ __forceinline__ void ldg_rs(float4* reg, const float* __restrict__ src,
                                       int ld, int kb, int K)
{
    int t = threadIdx.x;
    #pragma unroll
    for (int i = 0; i < ROWS/32; i++) {
        int m = i*32 + (t >> 3);
        int k = kb + (t & 7)*4;
        if (!KG || k < K) reg[i] = *(const float4*)&src[(size_t)m*ld + k];
        else              reg[i] = make_float4(0.f,0.f,0.f,0.f);
    }
}
template<int ROWS>
__device__ __forceinline__ void sts_rs(uint32_t* smp, const float4* reg)
{
    int t = threadIdx.x;
    #pragma unroll
    for (int i = 0; i < ROWS/32; i++) {
        int m = i*32 + (t >> 3);
        int k4 = t & 7;
        uint32_t* p = &smp[m*32 + ((k4 ^ (m & 7)) << 2)];
        p[0] = f2tf(reg[i].x); p[1] = f2tf(reg[i].y);
        p[2] = f2tf(reg[i].z); p[3] = f2tf(reg[i].w);
    }
}
template<bool NG, bool KG>
__device__ __forceinline__ void ldg_kn(float4* reg, const float* __restrict__ src,
                                       int ldb, int kb, int n0, int N, int K)
{
    int t = threadIdx.x;
    #pragma unroll
    for (int i = 0; i < 4; i++) {
        int r = i*8 + (t >> 5);
        int c = (t & 31)*4;
        bool ok = (!KG || (kb + r) < K) && (!NG || (n0 + c) < N);
        if (ok) reg[i] = *(const float4*)&src[(size_t)(kb+r)*ldb + n0 + c];
        else    reg[i] = make_float4(0.f,0.f,0.f,0.f);
    }
}
__device__ __forceinline__ void sts_kn(uint32_t* smp, const float4* reg)
{
    int t = threadIdx.x;
    #pragma unroll
    for (int i = 0; i < 4; i++) {
        int r = i*8 + (t >> 5);
        int c = (t & 31)*4;
        uint32_t* p = &smp[r*BSTRIDE + c];
        p[0] = f2tf(reg[i].x); p[1] = f2tf(reg[i].y);
        p[2] = f2tf(reg[i].z); p[3] = f2tf(reg[i].w);
    }
}
__device__ __forceinline__ void mma_chunk_kn(const uint32_t* smA, const uint32_t* smB,
                                             float acc[2][4][4],
                                             int warp_m, int warp_n, int lr, int lc)
{
    #pragma unroll
    for (int ks = 0; ks < 4; ks++) {
        int kb = ks*8, kb4 = ks*2;
        int swz = ((kb4 ^ lr) << 2) + lc;
        uint32_t b[4][2];
        #pragma unroll
        for (int j = 0; j < 4; j++) {
            int n = warp_n + j*8 + lr;
            b[j][0] = smB[(kb + lc)*BSTRIDE + n];
            b[j][1] = smB[(kb + 4 + lc)*BSTRIDE + n];
        }
        #pragma unroll
        for (int i = 0; i < 2; i++) {
            int mb = warp_m + i*16;
            uint32_t a0 = smA[(mb + lr)*32 + swz];
            uint32_t a1 = smA[(mb + 8 + lr)*32 + swz];
            uint32_t a2 = smA[(mb + lr)*32 + (swz ^ 4)];
            uint32_t a3 = smA[(mb + 8 + lr)*32 + (swz ^ 4)];
            #pragma unroll
            for (int j = 0; j < 4; j++)
                mma_tf32(acc[i][j], a0, a1, a2, a3, b[j][0], b[j][1]);
        }
    }
}
__device__ __forceinline__ void mma_chunk_rs(const uint32_t* smA, const uint32_t* smB,
                                             float acc[2][4][4],
                                             int warp_m, int warp_n, int lr, int lc)
{
    #pragma unroll
    for (int ks = 0; ks < 4; ks++) {
        int kb4 = ks*2;
        int swz = ((kb4 ^ lr) << 2) + lc;
        uint32_t b[4][2];
        #pragma unroll
        for (int j = 0; j < 4; j++) {
            int n = warp_n + j*8 + lr;
            b[j][0] = smB[n*32 + swz];
            b[j][1] = smB[n*32 + (swz ^ 4)];
        }
        #pragma unroll
        for (int i = 0; i < 2; i++) {
            int mb = warp_m + i*16;
            uint32_t a0 = smA[(mb + lr)*32 + swz];
            uint32_t a1 = smA[(mb + 8 + lr)*32 + swz];
            uint32_t a2 = smA[(mb + lr)*32 + (swz ^ 4)];
            uint32_t a3 = smA[(mb + 8 + lr)*32 + (swz ^ 4)];
            #pragma unroll
            for (int j = 0; j < 4; j++)
                mma_tf32(acc[i][j], a0, a1, a2, a3, b[j][0], b[j][1]);
        }
    }
}

__global__ __launch_bounds__(256)
void scores_tc(const float* __restrict__ Q, const float* __restrict__ Kc,
               float* __restrict__ attn)
{
    int zb = blockIdx.z, b = zb >> 3, h = zb & 7;
    int m0 = blockIdx.y * TMM, n0 = blockIdx.x * TNN;
    int t = threadIdx.x;
    float* S = attn + (size_t)zb*TT*TT;

    if (n0 > m0 + (TMM-1)) {
        int base = t*4;
        #pragma unroll
        for (int it = 0; it < 8; it++) {
            int e = base + it*1024;
            int r = e >> 7, cidx = e & 127;
            *(float4*)&S[(size_t)(m0+r)*TT + n0 + cidx] = make_float4(0.f,0.f,0.f,0.f);
        }
        return;
    }

    __shared__ uint32_t smA[TMM*32];
    __shared__ uint32_t smB[TNN*32];
    int wid = t >> 5, lane = t & 31;
    int lr = lane >> 2, lc = lane & 3;
    int warp_m = (wid & 1)*32, warp_n = (wid >> 1)*32;

    const float* Aq = Q  + (size_t)b*TT*CC + h*HD + (size_t)m0*CC;
    const float* Ak = Kc + (size_t)b*TT*CC + h*HD + (size_t)n0*CC;

    float acc[2][4][4] = {};
    float4 rA[2], rB[4];
    ldg_rs<TMM,false>(rA, Aq, CC, 0, HD);
    ldg_rs<TNN,false>(rB, Ak, CC, 0, HD);

    #pragma unroll
    for (int c = 0; c < HD/KC; c++) {
        sts_rs<TMM>(smA, rA);
        sts_rs<TNN>(smB, rB);
        __syncthreads();
        if (c + 1 < HD/KC) {
            ldg_rs<TMM,false>(rA, Aq, CC, (c+1)*KC, HD);
            ldg_rs<TNN,false>(rB, Ak, CC, (c+1)*KC, HD);
        }
        mma_chunk_rs(smA, smB, acc, warp_m, warp_n, lr, lc);
        __syncthreads();
    }

    float slope = exp2f(-(float)(h+1));
    #pragma unroll
    for (int i = 0; i < 2; i++) {
        int r0 = m0 + warp_m + i*16 + lr;
        #pragma unroll
        for (int j = 0; j < 4; j++) {
            int cg = n0 + warp_n + j*8 + 2*lc;
            float v0 = (cg   <= r0  ) ? acc[i][j][0]*SCALE + slope*(float)(cg  -r0  ) : 0.f;
            float v1 = (cg+1 <= r0  ) ? acc[i][j][1]*SCALE + slope*(float)(cg+1-r0  ) : 0.f;
            float v2 = (cg   <= r0+8) ? acc[i][j][2]*SCALE + slope*(float)(cg  -r0-8) : 0.f;
            float v3 = (cg+1 <= r0+8) ? acc[i][j][3]*SCALE + slope*(float)(cg+1-r0-8) : 0.f;
            *(float2*)&S[(size_t)r0*TT + cg]     = make_float2(v0, v1);
            *(float2*)&S[(size_t)(r0+8)*TT + cg] = make_float2(v2, v3);
        }
    }
}

__global__ void softmax_kernel(float* __restrict__ attnL)
{
    int rowid = blockIdx.x;
    int i = rowid & (TT-1);
    int L = i + 1;
    float* r = attnL + (size_t)rowid * TT;
    __shared__ float red[256];
    int tid = threadIdx.x;

    float m = -INFINITY;
    for (int c = tid; c < L; c += 256) m = fmaxf(m, r[c]);
    red[tid] = m; __syncthreads();
    for (int q = 128; q > 0; q >>= 1) { if (tid < q) red[tid] = fmaxf(red[tid], red[tid+q]); __syncthreads(); }
    m = red[0]; __syncthreads();

    float s = 0.f;
    for (int c = tid; c < L; c += 256) { float e = __expf(r[c]-m); r[c] = e; s += e; }
    red[tid] = s; __syncthreads();
    for (int q = 128; q > 0; q >>= 1) { if (tid < q) red[tid] += red[tid+q]; __syncthreads(); }
    float inv = 1.f / red[0];

    for (int c = tid; c < L; c += 256) r[c] *= inv;
}

__global__ __launch_bounds__(256)
void av_tc(const float* __restrict__ attn, const float* __restrict__ V,
           float* __restrict__ O)
{
    int zb = blockIdx.z, b = zb >> 3, h = zb & 7;
    int m0 = blockIdx.y * TMM;
    int t = threadIdx.x, wid = t >> 5, lane = t & 31;
    int lr = lane >> 2, lc = lane & 3;
    int warp_m = (wid & 1)*32, warp_n = (wid >> 1)*32;

    const float* A  = attn + (size_t)zb*TT*TT + (size_t)m0*TT;
    const float* Bv = V + (size_t)b*TT*CC + h*HD;
    float*       Co = O + (size_t)b*TT*CC + h*HD;

    __shared__ uint32_t smA[TMM*32];
    __shared__ uint32_t smB[KC*BSTRIDE];

    float acc[2][4][4] = {};
    float4 rA[2], rB[4];
    int nch = (m0 + TMM)/KC;

    ldg_rs<TMM,false>(rA, A, TT, 0, TT);
    ldg_kn<false,false>(rB, Bv, CC, 0, 0, HD, TT);

    for (int c = 0; c < nch; c++) {
        sts_rs<TMM>(smA, rA);
        sts_kn(smB, rB);
        __syncthreads();
        if (c + 1 < nch) {
            ldg_rs<TMM,false>(rA, A, TT, (c+1)*KC, TT);
            ldg_kn<false,false>(rB, Bv, CC, (c+1)*KC, 0, HD, TT);
        }
        mma_chunk_kn(smA, smB, acc, warp_m, warp_n, lr, lc);
        __syncthreads();
    }

    #pragma unroll
    for (int i = 0; i < 2; i++) {
        int r0 = m0 + warp_m + i*16 + lr;
        #pragma unroll
        for (int j = 0; j < 4; j++) {
            int cg = warp_n + j*8 + 2*lc;
            *(float2*)&Co[(size_t)r0*CC + cg]     = make_float2(acc[i][j][0], acc[i][j][1]);
            *(float2*)&Co[(size_t)(r0+8)*CC + cg] = make_float2(acc[i][j][2], acc[i][j][3]);
        }
    }
}

// ---------------- embedding / layernorm ----------------
__global__ void embed_kernel(const int* __restrict__ x, const float* __restrict__ emb,
                             float* __restrict__ h)
{
    int idx = blockIdx.x * 256 + threadIdx.x;
    int n = idx >> 8, c = idx & 255;
    ((float4*)h)[idx] = ((const float4*)emb)[(size_t)x[n]*(CC/4) + c];
}

__global__ void ln_kernel(const float* __restrict__ in, const float* __restrict__ g,
                          const float* __restrict__ b, float* __restrict__ out)
{
    int row = blockIdx.x, tid = threadIdx.x;
    const float4* xr = (const float4*)(in + (size_t)row*CC);
    float4 x = xr[tid];
    __shared__ float red[32];

    float s = x.x + x.y + x.z + x.w;
    #pragma unroll
    for (int o = 16; o; o >>= 1) s += __shfl_xor_sync(0xffffffffu, s, o);
    if ((tid & 31) == 0) red[tid >> 5] = s;
    __syncthreads();
    if (tid == 0) {
        float tsum = 0.f;
        #pragma unroll
        for (int w = 0; w < 8; w++) tsum += red[w];
        red[0] = tsum;
    }
    __syncthreads();
    float mu = red[0] * (1.f/CC);
    __syncthreads();

    float4 d = make_float4(x.x-mu, x.y-mu, x.z-mu, x.w-mu);
    float v = d.x*d.x + d.y*d.y + d.z*d.z + d.w*d.w;
    #pragma unroll
    for (int o = 16; o; o >>= 1) v += __shfl_xor_sync(0xffffffffu, v, o);
    if ((tid & 31) == 0) red[tid >> 5] = v;
    __syncthreads();
    if (tid == 0) {
        float tsum = 0.f;
        #pragma unroll
        for (int w = 0; w < 8; w++) tsum += red[w];
        red[0] = tsum;
    }
    __syncthreads();
    float rstd = rsqrtf(red[0] * (1.f/CC) + LN_EPS);

    float4 gg = ((const float4*)g)[tid];
    float4 bb = ((const float4*)b)[tid];
    float4 o4;
    o4.x = d.x*rstd*gg.x + bb.x;
    o4.y = d.y*rstd*gg.y + bb.y;
    o4.z = d.z*rstd*gg.z + bb.z;
    o4.w = d.w*rstd*gg.w + bb.w;
    ((float4*)(out + (size_t)row*CC))[tid] = o4;
}

// ---------------- host ----------------
extern "C" void kernel_launch(void* const* d_in, const int* in_sizes, int n_in,
                              void* d_out, int out_size)
{
    const int*   x    = (const int*)  d_in[0];
    const float* emb  = (const float*)d_in[1];
    const float* Wq   = (const float*)d_in[2];
    const float* bq   = (const float*)d_in[3];
    const float* Wk   = (const float*)d_in[4];
    const float* bk   = (const float*)d_in[5];
    const float* Wv   = (const float*)d_in[6];
    const float* bv   = (const float*)d_in[7];
    const float* Wo   = (const float*)d_in[8];
    const float* bo   = (const float*)d_in[9];
    const float* W1   = (const float*)d_in[10];
    const float* b1   = (const float*)d_in[11];
    const float* W2   = (const float*)d_in[12];
    const float* b2   = (const float*)d_in[13];
    const float* ln1g = (const float*)d_in[14];
    const float* ln1b = (const float*)d_in[15];
    const float* ln3g = (const float*)d_in[16];
    const float* ln3b = (const float*)d_in[17];
    const float* lnfg = (const float*)d_in[18];
    const float* lnfb = (const float*)d_in[19];
    const float* Wout = (const float*)d_in[20];
    const float* bout = (const float*)d_in[21];

    float* out_logits = (float*)d_out;                   // [B,T,V]
    float* out_attn   = out_logits + (size_t)BB*TT*VV;   // [L,B,H,T,T]

    float *h, *hn, *q, *k, *v, *o, *ff;
    cudaGetSymbolAddress((void**)&h,  g_h);
    cudaGetSymbolAddress((void**)&hn, g_hn);
    cudaGetSymbolAddress((void**)&q,  g_q);
    cudaGetSymbolAddress((void**)&k,  g_k);
    cudaGetSymbolAddress((void**)&v,  g_v);
    cudaGetSymbolAddress((void**)&o,  g_o);
    cudaGetSymbolAddress((void**)&ff, g_ff);

    embed_kernel<<<NTOK, 256>>>(x, emb, h);

    dim3 thr(256);
    dim3 gC(NTOK/GT, CC/GT);            // 16 x 8 (m on x -> B-stripe L2 reuse)
    dim3 gS(TT/TNN, TT/TMM, BB*HH);
    dim3 gAV(1, TT/TMM, BB*HH);
    dim3 gF1(NTOK/GT, 1);
    dim3 gL(NTOK/GT, VV/GT);            // 16 x 250

    for (int l = 0; l < LL; l++) {
        float* attnL = out_attn + (size_t)l*BB*HH*TT*TT;

        ln_kernel<<<NTOK, 256>>>(h, ln1g + l*CC, ln1b + l*CC, hn);

        gemm_h<false,false,false,false><<<gC, thr>>>(hn, CC, Wq + (size_t)l*CC*CC, CC,
                                                     bq + l*CC, nullptr, 0, q, CC, CC, CC);
        gemm_h<false,false,false,false><<<gC, thr>>>(hn, CC, Wk + (size_t)l*CC*CC, CC,
                                                     bk + l*CC, nullptr, 0, k, CC, CC, CC);
        gemm_h<false,false,false,false><<<gC, thr>>>(hn, CC, Wv + (size_t)l*CC*CC, CC,
                                                     bv + l*CC, nullptr, 0, v, CC, CC, CC);

        scores_tc<<<gS, thr>>>(q, k, attnL);
        softmax_kernel<<<BB*HH*TT, 256>>>(attnL);
        av_tc<<<gAV, thr>>>(attnL, v, o);

        gemm_h<false,true,false,false><<<gC, thr>>>(o, CC, Wo + (size_t)l*CC*CC, CC,
                                                    bo + l*CC, h, CC, h, CC, CC, CC);

        ln_kernel<<<NTOK, 256>>>(h, ln3g + l*CC, ln3b + l*CC, hn);

        gemm_h<true,false,true,false><<<gF1, thr>>>(hn, CC, W1 + (size_t)l*CC*FFD, FFD,
                                                    b1 + l*FFD, nullptr, 0, ff, FFP, FFD, CC);
        gemm_h<false,true,false,true><<<gC, thr>>>(ff, FFP, W2 + (size_t)l*FFD*CC, CC,
                                                   b2 + l*CC, h, CC, h, CC, CC, FFD);
    }

    ln_kernel<<<NTOK, 256>>>(h, lnfg, lnfb, hn);
    gemm_h<false,false,false,false><<<gL, thr>>>(hn, CC, Wout, VV,
                                                 bout, nullptr, 0, out_logits, VV, VV, CC);
}

// round 14
// speedup vs baseline: 1.5089x; 1.1584x over previous
#include <cuda_runtime.h>
#include <cuda_fp16.h>
#include <math.h>
#include <stdint.h>

#define BB 2
#define TT 1024
#define CC 1024
#define HH 8
#define HD 128
#define LL 4
#define FFD 100
#define FFP 128
#define VV 32000
#define NTOK (BB*TT)
#define SCALE 0.08838834764831845f
#define LN_EPS 1e-5f

/* ---- attn (mma.sync tf32) tiles ---- */
#define TMM 64
#define TNN 128
#define KC  32
#define BSTRIDE 136

/* ---- half dense gemm ---- */
#define GT   128
#define HKC  32
#define HROW 20           /* uint32 units per smem row: 16 data + 4 pad (80B) */
#define HSTAGE (128*HROW)

// ---------------- scratch ----------------
__device__ float  g_h  [NTOK*CC];
__device__ float  g_q  [NTOK*CC];
__device__ float  g_k  [NTOK*CC];
__device__ float  g_v  [NTOK*CC];
__device__ __half g_hn_h[NTOK*CC];
__device__ __half g_o_h [NTOK*CC];
__device__ __half g_ff_h[NTOK*FFP];
__device__ __half g_wtq[LL*CC*CC];
__device__ __half g_wtk[LL*CC*CC];
__device__ __half g_wtv[LL*CC*CC];
__device__ __half g_wto[LL*CC*CC];
__device__ __half g_wt1[LL*FFD*CC];
__device__ __half g_wt2[LL*CC*FFP];
__device__ __half g_wtout[(size_t)VV*CC];

// ---------------- helpers ----------------
__device__ __forceinline__ uint32_t f2tf(float f) {
    uint32_t r; asm("cvt.rna.tf32.f32 %0, %1;" : "=r"(r) : "f"(f)); return r;
}
__device__ __forceinline__ void mma_tf32(float c[4], uint32_t a0, uint32_t a1,
                                         uint32_t a2, uint32_t a3,
                                         uint32_t b0, uint32_t b1) {
    asm("mma.sync.aligned.m16n8k8.row.col.f32.tf32.tf32.f32 "
        "{%0,%1,%2,%3}, {%4,%5,%6,%7}, {%8,%9}, {%0,%1,%2,%3};"
        : "+f"(c[0]), "+f"(c[1]), "+f"(c[2]), "+f"(c[3])
        : "r"(a0), "r"(a1), "r"(a2), "r"(a3), "r"(b0), "r"(b1));
}
__device__ __forceinline__ void mma_f16(float c[4], const uint32_t a[4], const uint32_t b[2]) {
    asm("mma.sync.aligned.m16n8k16.row.col.f32.f16.f16.f32 "
        "{%0,%1,%2,%3}, {%4,%5,%6,%7}, {%8,%9}, {%0,%1,%2,%3};"
        : "+f"(c[0]), "+f"(c[1]), "+f"(c[2]), "+f"(c[3])
        : "r"(a[0]), "r"(a[1]), "r"(a[2]), "r"(a[3]), "r"(b[0]), "r"(b[1]));
}

// ---------------- weight convert+transpose: W[K][N] f32 -> Wt[N][Kp] half ----------------
__global__ void transpose_h(const float* __restrict__ W, __half* __restrict__ Wt,
                            int K, int N, int Kp, size_t inStride, size_t outStride)
{
    __shared__ float tile[32][33];
    int z = blockIdx.z;
    const float* src = W + (size_t)z * inStride;
    __half* dst = Wt + (size_t)z * outStride;
    int k0 = blockIdx.y * 32, n0 = blockIdx.x * 32;
    int tx = threadIdx.x, ty = threadIdx.y;
    #pragma unroll
    for (int i = ty; i < 32; i += 8) {
        int k = k0 + i, n = n0 + tx;
        tile[i][tx] = (k < K && n < N) ? src[(size_t)k * N + n] : 0.f;
    }
    __syncthreads();
    #pragma unroll
    for (int i = ty; i < 32; i += 8) {
        int n = n0 + i, k = k0 + tx;
        if (n < N && k < Kp) dst[(size_t)n * Kp + k] = __float2half(tile[tx][i]);
    }
}

// ================= half dense GEMM: C = A[MxK] * Bt^T, Bt half [N][ldb] =================
// A half row-major. grid = (M/128, ceil(N/128)). K multiple of 32.
template<bool RELU, bool ADD, bool OH>
__global__ __launch_bounds__(256, 2)
void gemm_hh(const __half* __restrict__ A, int lda,
             const __half* __restrict__ Bt, int ldb,
             const float* __restrict__ bias,
             const float* __restrict__ addp, int ldadd,
             float* __restrict__ C, __half* __restrict__ Ch, int ldc,
             int N, int K)
{
    __shared__ __align__(16) uint32_t smA[2*HSTAGE];
    __shared__ __align__(16) uint32_t smB[2*HSTAGE];
    int t = threadIdx.x, wid = t >> 5, lane = t & 31;
    int lr = lane >> 2, lc = lane & 3;
    int warp_m = (wid & 1) * 64, warp_n = (wid >> 1) * 32;
    int m0 = blockIdx.x * GT, n0 = blockIdx.y * GT;
    int nch = K / HKC;

    int row = t >> 1, off = (t & 1) * 16;   // 16-half groups
    const __half* Ap = A  + (size_t)(m0 + row) * lda + off;
    const __half* Bp = Bt + (size_t)(n0 + row) * ldb + off;
    bool bok = (n0 + row) < N;
    const uint4 z = make_uint4(0u, 0u, 0u, 0u);
    uint4 rA0, rA1, rB0, rB1;

    // load chunk 0
    rA0 = *(const uint4*)Ap;          rA1 = *(const uint4*)(Ap + 8);
    rB0 = bok ? *(const uint4*)Bp : z; rB1 = bok ? *(const uint4*)(Bp + 8) : z;

    // store chunk 0 -> buf 0
    {
        uint32_t* pA = smA + row * HROW + (off >> 1);
        *(uint4*)&pA[0] = rA0; *(uint4*)&pA[4] = rA1;
        uint32_t* pB = smB + row * HROW + (off >> 1);
        *(uint4*)&pB[0] = rB0; *(uint4*)&pB[4] = rB1;
    }
    __syncthreads();

    float acc[4][4][4] = {};

    for (int c = 0; c < nch; c++) {
        uint32_t cur = (c & 1) ? HSTAGE : 0;

        if (c + 1 < nch) {
            int k0 = (c + 1) * HKC;
            rA0 = *(const uint4*)(Ap + k0);      rA1 = *(const uint4*)(Ap + k0 + 8);
            rB0 = bok ? *(const uint4*)(Bp + k0) : z;
            rB1 = bok ? *(const uint4*)(Bp + k0 + 8) : z;
        }

        const uint32_t* sA = smA + cur;
        const uint32_t* sB = smB + cur;
        #pragma unroll
        for (int ks = 0; ks < 2; ks++) {
            int ko = ks * 8 + lc;
            uint32_t b[4][2];
            #pragma unroll
            for (int j = 0; j < 4; j++) {
                int nb = (warp_n + j * 8 + lr) * HROW;
                b[j][0] = sB[nb + ko];
                b[j][1] = sB[nb + ko + 4];
            }
            #pragma unroll
            for (int i = 0; i < 4; i++) {
                int mb = (warp_m + i * 16 + lr) * HROW;
                uint32_t a[4];
                a[0] = sA[mb + ko];
                a[1] = sA[mb + 8 * HROW + ko];
                a[2] = sA[mb + ko + 4];
                a[3] = sA[mb + 8 * HROW + ko + 4];
                #pragma unroll
                for (int j = 0; j < 4; j++)
                    mma_f16(acc[i][j], a, b[j]);
            }
        }

        if (c + 1 < nch) {
            uint32_t nxt = ((c + 1) & 1) ? HSTAGE : 0;
            uint32_t* pA = smA + nxt + row * HROW + (off >> 1);
            *(uint4*)&pA[0] = rA0; *(uint4*)&pA[4] = rA1;
            uint32_t* pB = smB + nxt + row * HROW + (off >> 1);
            *(uint4*)&pB[0] = rB0; *(uint4*)&pB[4] = rB1;
        }
        __syncthreads();
    }

    // ---- epilogue ----
    #pragma unroll
    for (int i = 0; i < 4; i++) {
        int r0 = m0 + warp_m + i * 16 + lr;
        #pragma unroll
        for (int j = 0; j < 4; j++) {
            int cg = n0 + warp_n + j * 8 + 2 * lc;
            if (cg < N) {
                float2 bb = *(const float2*)&bias[cg];
                float v0 = acc[i][j][0] + bb.x, v1 = acc[i][j][1] + bb.y;
                float v2 = acc[i][j][2] + bb.x, v3 = acc[i][j][3] + bb.y;
                if (ADD) {
                    float2 p0 = *(const float2*)&addp[(size_t)r0*ldadd + cg];
                    float2 p1 = *(const float2*)&addp[(size_t)(r0+8)*ldadd + cg];
                    v0 += p0.x; v1 += p0.y; v2 += p1.x; v3 += p1.y;
                }
                if (RELU) {
                    v0 = fmaxf(v0,0.f); v1 = fmaxf(v1,0.f);
                    v2 = fmaxf(v2,0.f); v3 = fmaxf(v3,0.f);
                }
                if (OH) {
                    *(__half2*)&Ch[(size_t)r0*ldc + cg]     = __floats2half2_rn(v0, v1);
                    *(__half2*)&Ch[(size_t)(r0+8)*ldc + cg] = __floats2half2_rn(v2, v3);
                } else {
                    *(float2*)&C[(size_t)r0*ldc + cg]     = make_float2(v0, v1);
                    *(float2*)&C[(size_t)(r0+8)*ldc + cg] = make_float2(v2, v3);
                }
            } else if (OH) {
                __half2 zz = __floats2half2_rn(0.f, 0.f);
                *(__half2*)&Ch[(size_t)r0*ldc + cg]     = zz;
                *(__half2*)&Ch[(size_t)(r0+8)*ldc + cg] = zz;
            }
        }
    }
}

// ================= attention path (mma.sync tf32) — proven =================
template<int ROWS, bool KG>
__device__ __forceinline__ void ldg_rs(float4* reg, const float* __restrict__ src,
                                       int ld, int kb, int K)
{
    int t = threadIdx.x;
    #pragma unroll
    for (int i = 0; i < ROWS/32; i++) {
        int m = i*32 + (t >> 3);
        int k = kb + (t & 7)*4;
        if (!KG || k < K) reg[i] = *(const float4*)&src[(size_t)m*ld + k];
        else              reg[i] = make_float4(0.f,0.f,0.f,0.f);
    }
}
template<int ROWS>
__device__ __forceinline__ void sts_rs(uint32_t* smp, const float4* reg)
{
    int t = threadIdx.x;
    #pragma unroll
    for (int i = 0; i < ROWS/32; i++) {
        int m = i*32 + (t >> 3);
        int k4 = t & 7;
        uint32_t* p = &smp[m*32 + ((k4 ^ (m & 7)) << 2)];
        p[0] = f2tf(reg[i].x); p[1] = f2tf(reg[i].y);
        p[2] = f2tf(reg[i].z); p[3] = f2tf(reg[i].w);
    }
}
template<bool NG, bool KG>
__device__ __forceinline__ void ldg_kn(float4* reg, const float* __restrict__ src,
                                       int ldb, int kb, int n0, int N, int K)
{
    int t = threadIdx.x;
    #pragma unroll
    for (int i = 0; i < 4; i++) {
        int r = i*8 + (t >> 5);
        int c = (t & 31)*4;
        bool ok = (!KG || (kb + r) < K) && (!NG || (n0 + c) < N);
        if (ok) reg[i] = *(const float4*)&src[(size_t)(kb+r)*ldb + n0 + c];
        else    reg[i] = make_float4(0.f,0.f,0.f,0.f);
    }
}
__device__ __forceinline__ void sts_kn(uint32_t* smp, const float4* reg)
{
    int t = threadIdx.x;
    #pragma unroll
    for (int i = 0; i < 4; i++) {
        int r = i*8 + (t >> 5);
        int c = (t & 31)*4;
        uint32_t* p = &smp[r*BSTRIDE + c];
        p[0] = f2tf(reg[i].x); p[1] = f2tf(reg[i].y);
        p[2] = f2tf(reg[i].z); p[3] = f2tf(reg[i].w);
    }
}
__device__ __forceinline__ void mma_chunk_kn(const uint32_t* smA, const uint32_t* smB,
                                             float acc[2][4][4],
                                             int warp_m, int warp_n, int lr, int lc)
{
    #pragma unroll
    for (int ks = 0; ks < 4; ks++) {
        int kb = ks*8, kb4 = ks*2;
        int swz = ((kb4 ^ lr) << 2) + lc;
        uint32_t b[4][2];
        #pragma unroll
        for (int j = 0; j < 4; j++) {
            int n = warp_n + j*8 + lr;
            b[j][0] = smB[(kb + lc)*BSTRIDE + n];
            b[j][1] = smB[(kb + 4 + lc)*BSTRIDE + n];
        }
        #pragma unroll
        for (int i = 0; i < 2; i++) {
            int mb = warp_m + i*16;
            uint32_t a0 = smA[(mb + lr)*32 + swz];
            uint32_t a1 = smA[(mb + 8 + lr)*32 + swz];
            uint32_t a2 = smA[(mb + lr)*32 + (swz ^ 4)];
            uint32_t a3 = smA[(mb + 8 + lr)*32 + (swz ^ 4)];
            #pragma unroll
            for (int j = 0; j < 4; j++)
                mma_tf32(acc[i][j], a0, a1, a2, a3, b[j][0], b[j][1]);
        }
    }
}
__device__ __forceinline__ void mma_chunk_rs(const uint32_t* smA, const uint32_t* smB,
                                             float acc[2][4][4],
                                             int warp_m, int warp_n, int lr, int lc)
{
    #pragma unroll
    for (int ks = 0; ks < 4; ks++) {
        int kb4 = ks*2;
        int swz = ((kb4 ^ lr) << 2) + lc;
        uint32_t b[4][2];
        #pragma unroll
        for (int j = 0; j < 4; j++) {
            int n = warp_n + j*8 + lr;
            b[j][0] = smB[n*32 + swz];
            b[j][1] = smB[n*32 + (swz ^ 4)];
        }
        #pragma unroll
        for (int i = 0; i < 2; i++) {
            int mb = warp_m + i*16;
            uint32_t a0 = smA[(mb + lr)*32 + swz];
            uint32_t a1 = smA[(mb + 8 + lr)*32 + swz];
            uint32_t a2 = smA[(mb + lr)*32 + (swz ^ 4)];
            uint32_t a3 = smA[(mb + 8 + lr)*32 + (swz ^ 4)];
            #pragma unroll
            for (int j = 0; j < 4; j++)
                mma_tf32(acc[i][j], a0, a1, a2, a3, b[j][0], b[j][1]);
        }
    }
}

__global__ __launch_bounds__(256)
void scores_tc(const float* __restrict__ Q, const float* __restrict__ Kc,
               float* __restrict__ attn)
{
    int zb = blockIdx.z, b = zb >> 3, h = zb & 7;
    int m0 = blockIdx.y * TMM, n0 = blockIdx.x * TNN;
    int t = threadIdx.x;
    float* S = attn + (size_t)zb*TT*TT;

    if (n0 > m0 + (TMM-1)) {
        int base = t*4;
        #pragma unroll
        for (int it = 0; it < 8; it++) {
            int e = base + it*1024;
            int r = e >> 7, cidx = e & 127;
            *(float4*)&S[(size_t)(m0+r)*TT + n0 + cidx] = make_float4(0.f,0.f,0.f,0.f);
        }
        return;
    }

    __shared__ uint32_t smA[TMM*32];
    __shared__ uint32_t smB[TNN*32];
    int wid = t >> 5, lane = t & 31;
    int lr = lane >> 2, lc = lane & 3;
    int warp_m = (wid & 1)*32, warp_n = (wid >> 1)*32;

    const float* Aq = Q  + (size_t)b*TT*CC + h*HD + (size_t)m0*CC;
    const float* Ak = Kc + (size_t)b*TT*CC + h*HD + (size_t)n0*CC;

    float acc[2][4][4] = {};
    float4 rA[2], rB[4];
    ldg_rs<TMM,false>(rA, Aq, CC, 0, HD);
    ldg_rs<TNN,false>(rB, Ak, CC, 0, HD);

    #pragma unroll
    for (int c = 0; c < HD/KC; c++) {
        sts_rs<TMM>(smA, rA);
        sts_rs<TNN>(smB, rB);
        __syncthreads();
        if (c + 1 < HD/KC) {
            ldg_rs<TMM,false>(rA, Aq, CC, (c+1)*KC, HD);
            ldg_rs<TNN,false>(rB, Ak, CC, (c+1)*KC, HD);
        }
        mma_chunk_rs(smA, smB, acc, warp_m, warp_n, lr, lc);
        __syncthreads();
    }

    float slope = exp2f(-(float)(h+1));
    #pragma unroll
    for (int i = 0; i < 2; i++) {
        int r0 = m0 + warp_m + i*16 + lr;
        #pragma unroll
        for (int j = 0; j < 4; j++) {
            int cg = n0 + warp_n + j*8 + 2*lc;
            float v0 = (cg   <= r0  ) ? acc[i][j][0]*SCALE + slope*(float)(cg  -r0  ) : 0.f;
            float v1 = (cg+1 <= r0  ) ? acc[i][j][1]*SCALE + slope*(float)(cg+1-r0  ) : 0.f;
            float v2 = (cg   <= r0+8) ? acc[i][j][2]*SCALE + slope*(float)(cg  -r0-8) : 0.f;
            float v3 = (cg+1 <= r0+8) ? acc[i][j][3]*SCALE + slope*(float)(cg+1-r0-8) : 0.f;
            *(float2*)&S[(size_t)r0*TT + cg]     = make_float2(v0, v1);
            *(float2*)&S[(size_t)(r0+8)*TT + cg] = make_float2(v2, v3);
        }
    }
}

__global__ void softmax_kernel(float* __restrict__ attnL)
{
    int rowid = blockIdx.x;
    int i = rowid & (TT-1);
    int L = i + 1;
    float* r = attnL + (size_t)rowid * TT;
    __shared__ float red[256];
    int tid = threadIdx.x;

    float m = -INFINITY;
    for (int c = tid; c < L; c += 256) m = fmaxf(m, r[c]);
    red[tid] = m; __syncthreads();
    for (int q = 128; q > 0; q >>= 1) { if (tid < q) red[tid] = fmaxf(red[tid], red[tid+q]); __syncthreads(); }
    m = red[0]; __syncthreads();

    float s = 0.f;
    for (int c = tid; c < L; c += 256) { float e = __expf(r[c]-m); r[c] = e; s += e; }
    red[tid] = s; __syncthreads();
    for (int q = 128; q > 0; q >>= 1) { if (tid < q) red[tid] += red[tid+q]; __syncthreads(); }
    float inv = 1.f / red[0];

    for (int c = tid; c < L; c += 256) r[c] *= inv;
}

// O = attn @ V -> writes HALF (consumed by Wo gemm)
__global__ __launch_bounds__(256)
void av_tc(const float* __restrict__ attn, const float* __restrict__ V,
           __half* __restrict__ O)
{
    int zb = blockIdx.z, b = zb >> 3, h = zb & 7;
    int m0 = blockIdx.y * TMM;
    int t = threadIdx.x, wid = t >> 5, lane = t & 31;
    int lr = lane >> 2, lc = lane & 3;
    int warp_m = (wid & 1)*32, warp_n = (wid >> 1)*32;

    const float* A  = attn + (size_t)zb*TT*TT + (size_t)m0*TT;
    const float* Bv = V + (size_t)b*TT*CC + h*HD;
    __half*      Co = O + (size_t)b*TT*CC + h*HD;

    __shared__ uint32_t smA[TMM*32];
    __shared__ uint32_t smB[KC*BSTRIDE];

    float acc[2][4][4] = {};
    float4 rA[2], rB[4];
    int nch = (m0 + TMM)/KC;

    ldg_rs<TMM,false>(rA, A, TT, 0, TT);
    ldg_kn<false,false>(rB, Bv, CC, 0, 0, HD, TT);

    for (int c = 0; c < nch; c++) {
        sts_rs<TMM>(smA, rA);
        sts_kn(smB, rB);
        __syncthreads();
        if (c + 1 < nch) {
            ldg_rs<TMM,false>(rA, A, TT, (c+1)*KC, TT);
            ldg_kn<false,false>(rB, Bv, CC, (c+1)*KC, 0, HD, TT);
        }
        mma_chunk_kn(smA, smB, acc, warp_m, warp_n, lr, lc);
        __syncthreads();
    }

    #pragma unroll
    for (int i = 0; i < 2; i++) {
        int r0 = m0 + warp_m + i*16 + lr;
        #pragma unroll
        for (int j = 0; j < 4; j++) {
            int cg = warp_n + j*8 + 2*lc;
            *(__half2*)&Co[(size_t)r0*CC + cg]     = __floats2half2_rn(acc[i][j][0], acc[i][j][1]);
            *(__half2*)&Co[(size_t)(r0+8)*CC + cg] = __floats2half2_rn(acc[i][j][2], acc[i][j][3]);
        }
    }
}

// ---------------- embedding / layernorm ----------------
__global__ void embed_kernel(const int* __restrict__ x, const float* __restrict__ emb,
                             float* __restrict__ h)
{
    int idx = blockIdx.x * 256 + threadIdx.x;
    int n = idx >> 8, c = idx & 255;
    ((float4*)h)[idx] = ((const float4*)emb)[(size_t)x[n]*(CC/4) + c];
}

// LN: float in -> HALF out (consumed by gemms only)
__global__ void ln_kernel(const float* __restrict__ in, const float* __restrict__ g,
                          const float* __restrict__ b, __half* __restrict__ out)
{
    int row = blockIdx.x, tid = threadIdx.x;
    const float4* xr = (const float4*)(in + (size_t)row*CC);
    float4 x = xr[tid];
    __shared__ float red[32];

    float s = x.x + x.y + x.z + x.w;
    #pragma unroll
    for (int o = 16; o; o >>= 1) s += __shfl_xor_sync(0xffffffffu, s, o);
    if ((tid & 31) == 0) red[tid >> 5] = s;
    __syncthreads();
    if (tid == 0) {
        float tsum = 0.f;
        #pragma unroll
        for (int w = 0; w < 8; w++) tsum += red[w];
        red[0] = tsum;
    }
    __syncthreads();
    float mu = red[0] * (1.f/CC);
    __syncthreads();

    float4 d = make_float4(x.x-mu, x.y-mu, x.z-mu, x.w-mu);
    float v = d.x*d.x + d.y*d.y + d.z*d.z + d.w*d.w;
    #pragma unroll
    for (int o = 16; o; o >>= 1) v += __shfl_xor_sync(0xffffffffu, v, o);
    if ((tid & 31) == 0) red[tid >> 5] = v;
    __syncthreads();
    if (tid == 0) {
        float tsum = 0.f;
        #pragma unroll
        for (int w = 0; w < 8; w++) tsum += red[w];
        red[0] = tsum;
    }
    __syncthreads();
    float rstd = rsqrtf(red[0] * (1.f/CC) + LN_EPS);

    float4 gg = ((const float4*)g)[tid];
    float4 bb = ((const float4*)b)[tid];
    __half2 h0 = __floats2half2_rn(d.x*rstd*gg.x + bb.x, d.y*rstd*gg.y + bb.y);
    __half2 h1 = __floats2half2_rn(d.z*rstd*gg.z + bb.z, d.w*rstd*gg.w + bb.w);
    uint2 pk; pk.x = *(uint32_t*)&h0; pk.y = *(uint32_t*)&h1;
    *(uint2*)&out[(size_t)row*CC + tid*4] = pk;
}

// ---------------- host ----------------
extern "C" void kernel_launch(void* const* d_in, const int* in_sizes, int n_in,
                              void* d_out, int out_size)
{
    const int*   x    = (const int*)  d_in[0];
    const float* emb  = (const float*)d_in[1];
    const float* Wq   = (const float*)d_in[2];
    const float* bq   = (const float*)d_in[3];
    const float* Wk   = (const float*)d_in[4];
    const float* bk   = (const float*)d_in[5];
    const float* Wv   = (const float*)d_in[6];
    const float* bv   = (const float*)d_in[7];
    const float* Wo   = (const float*)d_in[8];
    const float* bo   = (const float*)d_in[9];
    const float* W1   = (const float*)d_in[10];
    const float* b1   = (const float*)d_in[11];
    const float* W2   = (const float*)d_in[12];
    const float* b2   = (const float*)d_in[13];
    const float* ln1g = (const float*)d_in[14];
    const float* ln1b = (const float*)d_in[15];
    const float* ln3g = (const float*)d_in[16];
    const float* ln3b = (const float*)d_in[17];
    const float* lnfg = (const float*)d_in[18];
    const float* lnfb = (const float*)d_in[19];
    const float* Wout = (const float*)d_in[20];
    const float* bout = (const float*)d_in[21];

    float* out_logits = (float*)d_out;                   // [B,T,V]
    float* out_attn   = out_logits + (size_t)BB*TT*VV;   // [L,B,H,T,T]

    float *h, *q, *k, *v;
    __half *hn_h, *o_h, *ff_h, *wtq, *wtk, *wtv, *wto, *wt1, *wt2, *wtout;
    cudaGetSymbolAddress((void**)&h,    g_h);
    cudaGetSymbolAddress((void**)&q,    g_q);
    cudaGetSymbolAddress((void**)&k,    g_k);
    cudaGetSymbolAddress((void**)&v,    g_v);
    cudaGetSymbolAddress((void**)&hn_h, g_hn_h);
    cudaGetSymbolAddress((void**)&o_h,  g_o_h);
    cudaGetSymbolAddress((void**)&ff_h, g_ff_h);
    cudaGetSymbolAddress((void**)&wtq,  g_wtq);
    cudaGetSymbolAddress((void**)&wtk,  g_wtk);
    cudaGetSymbolAddress((void**)&wtv,  g_wtv);
    cudaGetSymbolAddress((void**)&wto,  g_wto);
    cudaGetSymbolAddress((void**)&wt1,  g_wt1);
    cudaGetSymbolAddress((void**)&wt2,  g_wt2);
    cudaGetSymbolAddress((void**)&wtout,g_wtout);

    dim3 tt(32, 8);
    // weight convert+transpose pre-pass (runs inside graph; deterministic)
    transpose_h<<<dim3(CC/32, CC/32, LL), tt>>>(Wq, wtq, CC, CC, CC, (size_t)CC*CC, (size_t)CC*CC);
    transpose_h<<<dim3(CC/32, CC/32, LL), tt>>>(Wk, wtk, CC, CC, CC, (size_t)CC*CC, (size_t)CC*CC);
    transpose_h<<<dim3(CC/32, CC/32, LL), tt>>>(Wv, wtv, CC, CC, CC, (size_t)CC*CC, (size_t)CC*CC);
    transpose_h<<<dim3(CC/32, CC/32, LL), tt>>>(Wo, wto, CC, CC, CC, (size_t)CC*CC, (size_t)CC*CC);
    transpose_h<<<dim3(4, CC/32, LL), tt>>>(W1, wt1, CC, FFD, CC, (size_t)CC*FFD, (size_t)FFD*CC);
    transpose_h<<<dim3(CC/32, FFP/32, LL), tt>>>(W2, wt2, FFD, CC, FFP, (size_t)FFD*CC, (size_t)CC*FFP);
    transpose_h<<<dim3(VV/32, CC/32, 1), tt>>>(Wout, wtout, CC, VV, CC, 0, 0);

    embed_kernel<<<NTOK, 256>>>(x, emb, h);

    dim3 thr(256);
    dim3 gC(NTOK/GT, CC/GT);            // 16 x 8
    dim3 gS(TT/TNN, TT/TMM, BB*HH);
    dim3 gAV(1, TT/TMM, BB*HH);
    dim3 gF1(NTOK/GT, 1);
    dim3 gL(NTOK/GT, VV/GT);            // 16 x 250

    for (int l = 0; l < LL; l++) {
        float* attnL = out_attn + (size_t)l*BB*HH*TT*TT;

        ln_kernel<<<NTOK, 256>>>(h, ln1g + l*CC, ln1b + l*CC, hn_h);

        gemm_hh<false,false,false><<<gC, thr>>>(hn_h, CC, wtq + (size_t)l*CC*CC, CC,
                                                bq + l*CC, nullptr, 0, q, nullptr, CC, CC, CC);
        gemm_hh<false,false,false><<<gC, thr>>>(hn_h, CC, wtk + (size_t)l*CC*CC, CC,
                                                bk + l*CC, nullptr, 0, k, nullptr, CC, CC, CC);
        gemm_hh<false,false,false><<<gC, thr>>>(hn_h, CC, wtv + (size_t)l*CC*CC, CC,
                                                bv + l*CC, nullptr, 0, v, nullptr, CC, CC, CC);

        scores_tc<<<gS, thr>>>(q, k, attnL);
        softmax_kernel<<<BB*HH*TT, 256>>>(attnL);
        av_tc<<<gAV, thr>>>(attnL, v, o_h);

        // h = h + o @ Wo + bo
        gemm_hh<false,true,false><<<gC, thr>>>(o_h, CC, wto + (size_t)l*CC*CC, CC,
                                               bo + l*CC, h, CC, h, nullptr, CC, CC, CC);

        ln_kernel<<<NTOK, 256>>>(h, ln3g + l*CC, ln3b + l*CC, hn_h);

        // ff = relu(hn @ W1 + b1) -> half, pad cols zeroed
        gemm_hh<true,false,true><<<gF1, thr>>>(hn_h, CC, wt1 + (size_t)l*FFD*CC, CC,
                                               b1 + l*FFD, nullptr, 0, nullptr, ff_h, FFP, FFD, CC);
        // h = h + ff @ W2 + b2 (K padded to 128, pads zero on B side)
        gemm_hh<false,true,false><<<gC, thr>>>(ff_h, FFP, wt2 + (size_t)l*CC*FFP, FFP,
                                               b2 + l*CC, h, CC, h, nullptr, CC, CC, FFP);
    }

    ln_kernel<<<NTOK, 256>>>(h, lnfg, lnfb, hn_h);
    gemm_hh<false,false,false><<<gL, thr>>>(hn_h, CC, wtout, CC,
                                            bout, nullptr, 0, out_logits, nullptr, VV, VV, CC);
}

// round 16
// speedup vs baseline: 1.5776x; 1.0455x over previous
#include <cuda_runtime.h>
#include <cuda_fp16.h>
#include <math.h>
#include <stdint.h>

#define BB 2
#define TT 1024
#define CC 1024
#define HH 8
#define HD 128
#define LL 4
#define FFD 100
#define FFP 128
#define VV 32000
#define NTOK (BB*TT)
#define SCALE 0.08838834764831845f
#define LN_EPS 1e-5f

/* ---- attn tiles ---- */
#define TMM 64
#define TNN 128
#define KC  32
#define BSTRIDE 136
#define SHR 68            /* uint32 row stride for half attn smem (64 data + 4 pad) */
#define SCORES_SMEM ((TMM + TNN) * SHR * 4)

/* ---- half dense gemm ---- */
#define GT   128
#define HKC  32
#define HROW 20
#define HSTAGE (128*HROW)

// ---------------- scratch ----------------
__device__ float  g_h  [NTOK*CC];
__device__ float  g_v  [NTOK*CC];
__device__ __half g_q_h[NTOK*CC];
__device__ __half g_k_h[NTOK*CC];
__device__ __half g_hn_h[NTOK*CC];
__device__ __half g_o_h [NTOK*CC];
__device__ __half g_ff_h[NTOK*FFP];
__device__ __half g_wtq[LL*CC*CC];
__device__ __half g_wtk[LL*CC*CC];
__device__ __half g_wtv[LL*CC*CC];
__device__ __half g_wto[LL*CC*CC];
__device__ __half g_wt1[LL*FFD*CC];
__device__ __half g_wt2[LL*CC*FFP];
__device__ __half g_wtout[(size_t)VV*CC];

// ---------------- helpers ----------------
__device__ __forceinline__ uint32_t f2tf(float f) {
    uint32_t r; asm("cvt.rna.tf32.f32 %0, %1;" : "=r"(r) : "f"(f)); return r;
}
__device__ __forceinline__ void mma_tf32(float c[4], uint32_t a0, uint32_t a1,
                                         uint32_t a2, uint32_t a3,
                                         uint32_t b0, uint32_t b1) {
    asm("mma.sync.aligned.m16n8k8.row.col.f32.tf32.tf32.f32 "
        "{%0,%1,%2,%3}, {%4,%5,%6,%7}, {%8,%9}, {%0,%1,%2,%3};"
        : "+f"(c[0]), "+f"(c[1]), "+f"(c[2]), "+f"(c[3])
        : "r"(a0), "r"(a1), "r"(a2), "r"(a3), "r"(b0), "r"(b1));
}
__device__ __forceinline__ void mma_f16(float c[4], const uint32_t a[4], const uint32_t b[2]) {
    asm("mma.sync.aligned.m16n8k16.row.col.f32.f16.f16.f32 "
        "{%0,%1,%2,%3}, {%4,%5,%6,%7}, {%8,%9}, {%0,%1,%2,%3};"
        : "+f"(c[0]), "+f"(c[1]), "+f"(c[2]), "+f"(c[3])
        : "r"(a[0]), "r"(a[1]), "r"(a[2]), "r"(a[3]), "r"(b[0]), "r"(b[1]));
}

// ---------------- fast transpose: W[K][N] f32 -> Wt[N][Kp] half, 64x64 tiles ----------------
__global__ void transpose_h(const float* __restrict__ W, __half* __restrict__ Wt,
                            int K, int N, int Kp, size_t inStride, size_t outStride)
{
    __shared__ float tile[64][65];
    const float* src = W + (size_t)blockIdx.z * inStride;
    __half* dst = Wt + (size_t)blockIdx.z * outStride;
    int k0 = blockIdx.y * 64, n0 = blockIdx.x * 64;
    int t = threadIdx.x;
    int lr = t >> 4, lcv = (t & 15) * 4;

    #pragma unroll
    for (int p = 0; p < 4; p++) {
        int kr = lr + p * 16;
        int k = k0 + kr, n = n0 + lcv;
        float4 v = make_float4(0.f, 0.f, 0.f, 0.f);
        if (k < K) {
            if (n + 3 < N) v = *(const float4*)&src[(size_t)k * N + n];
            else {
                if (n   < N) v.x = src[(size_t)k * N + n];
                if (n+1 < N) v.y = src[(size_t)k * N + n + 1];
                if (n+2 < N) v.z = src[(size_t)k * N + n + 2];
                if (n+3 < N) v.w = src[(size_t)k * N + n + 3];
            }
        }
        tile[kr][lcv] = v.x; tile[kr][lcv+1] = v.y;
        tile[kr][lcv+2] = v.z; tile[kr][lcv+3] = v.w;
    }
    __syncthreads();

    int n = t >> 2, kg = (t & 3) * 16;
    int gn = n0 + n, gk = k0 + kg;
    if (gn < N) {
        uint32_t buf[8];
        #pragma unroll
        for (int j = 0; j < 8; j++) {
            __half2 hh = __floats2half2_rn(tile[kg + 2*j][n], tile[kg + 2*j + 1][n]);
            buf[j] = *(uint32_t*)&hh;
        }
        if (gk + 15 < Kp) {
            *(uint4*)&dst[(size_t)gn * Kp + gk]     = *(uint4*)&buf[0];
            *(uint4*)&dst[(size_t)gn * Kp + gk + 8] = *(uint4*)&buf[4];
        } else {
            for (int j = 0; j < 16; j++)
                if (gk + j < Kp)
                    dst[(size_t)gn * Kp + gk + j] = ((__half*)buf)[j];
        }
    }
}

// ================= half dense GEMM =================
template<bool RELU, bool ADD, bool OH>
__global__ __launch_bounds__(256, 2)
void gemm_hh(const __half* __restrict__ A, int lda,
             const __half* __restrict__ Bt, int ldb,
             const float* __restrict__ bias,
             const float* __restrict__ addp, int ldadd,
             float* __restrict__ C, __half* __restrict__ Ch, int ldc,
             int N, int K)
{
    __shared__ __align__(16) uint32_t smA[2*HSTAGE];
    __shared__ __align__(16) uint32_t smB[2*HSTAGE];
    int t = threadIdx.x, wid = t >> 5, lane = t & 31;
    int lr = lane >> 2, lc = lane & 3;
    int warp_m = (wid & 1) * 64, warp_n = (wid >> 1) * 32;
    int m0 = blockIdx.x * GT, n0 = blockIdx.y * GT;
    int nch = K / HKC;

    int row = t >> 1, off = (t & 1) * 16;
    const __half* Ap = A  + (size_t)(m0 + row) * lda + off;
    const __half* Bp = Bt + (size_t)(n0 + row) * ldb + off;
    bool bok = (n0 + row) < N;
    const uint4 z = make_uint4(0u, 0u, 0u, 0u);
    uint4 rA0, rA1, rB0, rB1;

    rA0 = *(const uint4*)Ap;          rA1 = *(const uint4*)(Ap + 8);
    rB0 = bok ? *(const uint4*)Bp : z; rB1 = bok ? *(const uint4*)(Bp + 8) : z;

    {
        uint32_t* pA = smA + row * HROW + (off >> 1);
        *(uint4*)&pA[0] = rA0; *(uint4*)&pA[4] = rA1;
        uint32_t* pB = smB + row * HROW + (off >> 1);
        *(uint4*)&pB[0] = rB0; *(uint4*)&pB[4] = rB1;
    }
    __syncthreads();

    float acc[4][4][4] = {};

    for (int c = 0; c < nch; c++) {
        uint32_t cur = (c & 1) ? HSTAGE : 0;

        if (c + 1 < nch) {
            int k0 = (c + 1) * HKC;
            rA0 = *(const uint4*)(Ap + k0);      rA1 = *(const uint4*)(Ap + k0 + 8);
            rB0 = bok ? *(const uint4*)(Bp + k0) : z;
            rB1 = bok ? *(const uint4*)(Bp + k0 + 8) : z;
        }

        const uint32_t* sA = smA + cur;
        const uint32_t* sB = smB + cur;
        #pragma unroll
        for (int ks = 0; ks < 2; ks++) {
            int ko = ks * 8 + lc;
            uint32_t b[4][2];
            #pragma unroll
            for (int j = 0; j < 4; j++) {
                int nb = (warp_n + j * 8 + lr) * HROW;
                b[j][0] = sB[nb + ko];
                b[j][1] = sB[nb + ko + 4];
            }
            #pragma unroll
            for (int i = 0; i < 4; i++) {
                int mb = (warp_m + i * 16 + lr) * HROW;
                uint32_t a[4];
                a[0] = sA[mb + ko];
                a[1] = sA[mb + 8 * HROW + ko];
                a[2] = sA[mb + ko + 4];
                a[3] = sA[mb + 8 * HROW + ko + 4];
                #pragma unroll
                for (int j = 0; j < 4; j++)
                    mma_f16(acc[i][j], a, b[j]);
            }
        }

        if (c + 1 < nch) {
            uint32_t nxt = ((c + 1) & 1) ? HSTAGE : 0;
            uint32_t* pA = smA + nxt + row * HROW + (off >> 1);
            *(uint4*)&pA[0] = rA0; *(uint4*)&pA[4] = rA1;
            uint32_t* pB = smB + nxt + row * HROW + (off >> 1);
            *(uint4*)&pB[0] = rB0; *(uint4*)&pB[4] = rB1;
        }
        __syncthreads();
    }

    #pragma unroll
    for (int i = 0; i < 4; i++) {
        int r0 = m0 + warp_m + i * 16 + lr;
        #pragma unroll
        for (int j = 0; j < 4; j++) {
            int cg = n0 + warp_n + j * 8 + 2 * lc;
            if (cg < N) {
                float2 bb = *(const float2*)&bias[cg];
                float v0 = acc[i][j][0] + bb.x, v1 = acc[i][j][1] + bb.y;
                float v2 = acc[i][j][2] + bb.x, v3 = acc[i][j][3] + bb.y;
                if (ADD) {
                    float2 p0 = *(const float2*)&addp[(size_t)r0*ldadd + cg];
                    float2 p1 = *(const float2*)&addp[(size_t)(r0+8)*ldadd + cg];
                    v0 += p0.x; v1 += p0.y; v2 += p1.x; v3 += p1.y;
                }
                if (RELU) {
                    v0 = fmaxf(v0,0.f); v1 = fmaxf(v1,0.f);
                    v2 = fmaxf(v2,0.f); v3 = fmaxf(v3,0.f);
                }
                if (OH) {
                    *(__half2*)&Ch[(size_t)r0*ldc + cg]     = __floats2half2_rn(v0, v1);
                    *(__half2*)&Ch[(size_t)(r0+8)*ldc + cg] = __floats2half2_rn(v2, v3);
                } else {
                    *(float2*)&C[(size_t)r0*ldc + cg]     = make_float2(v0, v1);
                    *(float2*)&C[(size_t)(r0+8)*ldc + cg] = make_float2(v2, v3);
                }
            } else if (OH) {
                __half2 zz = __floats2half2_rn(0.f, 0.f);
                *(__half2*)&Ch[(size_t)r0*ldc + cg]     = zz;
                *(__half2*)&Ch[(size_t)(r0+8)*ldc + cg] = zz;
            }
        }
    }
}

// ================= scores on fp16: S = Q K^T * scale + alibi; 0 above diag =================
__global__ __launch_bounds__(256)
void scores_h(const __half* __restrict__ Q, const __half* __restrict__ Kh,
              float* __restrict__ attn)
{
    int zb = blockIdx.z, b = zb >> 3, h = zb & 7;
    int m0 = blockIdx.y * TMM, n0 = blockIdx.x * TNN;
    int t = threadIdx.x;
    float* S = attn + (size_t)zb*TT*TT;

    if (n0 > m0 + (TMM-1)) {
        int base = t*4;
        #pragma unroll
        for (int it = 0; it < 8; it++) {
            int e = base + it*1024;
            int r = e >> 7, cidx = e & 127;
            *(float4*)&S[(size_t)(m0+r)*TT + n0 + cidx] = make_float4(0.f,0.f,0.f,0.f);
        }
        return;
    }

    extern __shared__ uint32_t ssm[];
    uint32_t* sA = ssm;
    uint32_t* sB = ssm + TMM * SHR;
    int wid = t >> 5, lane = t & 31;
    int lr = lane >> 2, lc = lane & 3;
    int warp_m = (wid & 1)*32, warp_n = (wid >> 1)*32;

    const __half* Aq = Q  + (size_t)b*TT*CC + h*HD + (size_t)m0*CC;
    const __half* Ak = Kh + (size_t)b*TT*CC + h*HD + (size_t)n0*CC;

    // fill A: 64 rows x 128 halves (4 threads/row, 4 uint4 each)
    {
        int r = t >> 2, pt = t & 3;
        const uint4* gp = (const uint4*)(Aq + (size_t)r*CC + pt*32);
        uint32_t* sp = sA + r*SHR + pt*16;
        uint4 v0 = gp[0], v1 = gp[1], v2 = gp[2], v3 = gp[3];
        *(uint4*)&sp[0] = v0; *(uint4*)&sp[4] = v1;
        *(uint4*)&sp[8] = v2; *(uint4*)&sp[12] = v3;
    }
    // fill B: 128 rows x 128 halves (2 threads/row, 8 uint4 each)
    {
        int r = t >> 1, pt = t & 1;
        const uint4* gp = (const uint4*)(Ak + (size_t)r*CC + pt*64);
        uint32_t* sp = sB + r*SHR + pt*32;
        #pragma unroll
        for (int j = 0; j < 8; j++) *(uint4*)&sp[4*j] = gp[j];
    }
    __syncthreads();

    float acc[2][4][4] = {};
    #pragma unroll
    for (int ks = 0; ks < 8; ks++) {
        int ko = ks * 8 + lc;
        uint32_t b2[4][2];
        #pragma unroll
        for (int j = 0; j < 4; j++) {
            int nb = (warp_n + j*8 + lr) * SHR;
            b2[j][0] = sB[nb + ko];
            b2[j][1] = sB[nb + ko + 4];
        }
        #pragma unroll
        for (int i = 0; i < 2; i++) {
            int mb = (warp_m + i*16 + lr) * SHR;
            uint32_t a[4];
            a[0] = sA[mb + ko];
            a[1] = sA[mb + 8*SHR + ko];
            a[2] = sA[mb + ko + 4];
            a[3] = sA[mb + 8*SHR + ko + 4];
            #pragma unroll
            for (int j = 0; j < 4; j++)
                mma_f16(acc[i][j], a, b2[j]);
        }
    }

    float slope = exp2f(-(float)(h+1));
    #pragma unroll
    for (int i = 0; i < 2; i++) {
        int r0 = m0 + warp_m + i*16 + lr;
        #pragma unroll
        for (int j = 0; j < 4; j++) {
            int cg = n0 + warp_n + j*8 + 2*lc;
            float v0 = (cg   <= r0  ) ? acc[i][j][0]*SCALE + slope*(float)(cg  -r0  ) : 0.f;
            float v1 = (cg+1 <= r0  ) ? acc[i][j][1]*SCALE + slope*(float)(cg+1-r0  ) : 0.f;
            float v2 = (cg   <= r0+8) ? acc[i][j][2]*SCALE + slope*(float)(cg  -r0-8) : 0.f;
            float v3 = (cg+1 <= r0+8) ? acc[i][j][3]*SCALE + slope*(float)(cg+1-r0-8) : 0.f;
            *(float2*)&S[(size_t)r0*TT + cg]     = make_float2(v0, v1);
            *(float2*)&S[(size_t)(r0+8)*TT + cg] = make_float2(v2, v3);
        }
    }
}

// ================= softmax: online 2-pass =================
__global__ void softmax_kernel(float* __restrict__ attnL)
{
    int rowid = blockIdx.x;
    int i = rowid & (TT-1);
    int L = i + 1;
    float* r = attnL + (size_t)rowid * TT;
    __shared__ float redm[256], reds[256];
    int tid = threadIdx.x;

    float m = -INFINITY, s = 0.f;
    for (int c = tid; c < L; c += 256) {
        float xv = r[c];
        if (xv > m) { s = s * __expf(m - xv) + 1.f; m = xv; }
        else        s += __expf(xv - m);
    }
    redm[tid] = m; reds[tid] = s; __syncthreads();
    for (int q = 128; q > 0; q >>= 1) {
        if (tid < q) {
            float m1 = redm[tid], s1 = reds[tid];
            float m2 = redm[tid+q], s2 = reds[tid+q];
            float M = fmaxf(m1, m2);
            float w1 = (m1 == -INFINITY) ? 0.f : __expf(m1 - M);
            float w2 = (m2 == -INFINITY) ? 0.f : __expf(m2 - M);
            reds[tid] = s1 * w1 + s2 * w2;
            redm[tid] = M;
        }
        __syncthreads();
    }
    float M = redm[0];
    float inv = 1.f / reds[0];

    for (int c = tid; c < L; c += 256) r[c] = __expf(r[c] - M) * inv;
}

// ================= attn tf32 helpers (av path) =================
template<int ROWS, bool KG>
__device__ __forceinline__ void ldg_rs(float4* reg, const float* __restrict__ src,
                                       int ld, int kb, int K)
{
    int t = threadIdx.x;
    #pragma unroll
    for (int i = 0; i < ROWS/32; i++) {
        int m = i*32 + (t >> 3);
        int k = kb + (t & 7)*4;
        if (!KG || k < K) reg[i] = *(const float4*)&src[(size_t)m*ld + k];
        else              reg[i] = make_float4(0.f,0.f,0.f,0.f);
    }
}
template<int ROWS>
__device__ __forceinline__ void sts_rs(uint32_t* smp, const float4* reg)
{
    int t = threadIdx.x;
    #pragma unroll
    for (int i = 0; i < ROWS/32; i++) {
        int m = i*32 + (t >> 3);
        int k4 = t & 7;
        uint32_t* p = &smp[m*32 + ((k4 ^ (m & 7)) << 2)];
        p[0] = f2tf(reg[i].x); p[1] = f2tf(reg[i].y);
        p[2] = f2tf(reg[i].z); p[3] = f2tf(reg[i].w);
    }
}
template<bool NG, bool KG>
__device__ __forceinline__ void ldg_kn(float4* reg, const float* __restrict__ src,
                                       int ldb, int kb, int n0, int N, int K)
{
    int t = threadIdx.x;
    #pragma unroll
    for (int i = 0; i < 4; i++) {
        int r = i*8 + (t >> 5);
        int c = (t & 31)*4;
        bool ok = (!KG || (kb + r) < K) && (!NG || (n0 + c) < N);
        if (ok) reg[i] = *(const float4*)&src[(size_t)(kb+r)*ldb + n0 + c];
        else    reg[i] = make_float4(0.f,0.f,0.f,0.f);
    }
}
__device__ __forceinline__ void sts_kn(uint32_t* smp, const float4* reg)
{
    int t = threadIdx.x;
    #pragma unroll
    for (int i = 0; i < 4; i++) {
        int r = i*8 + (t >> 5);
        int c = (t & 31)*4;
        uint32_t* p = &smp[r*BSTRIDE + c];
        p[0] = f2tf(reg[i].x); p[1] = f2tf(reg[i].y);
        p[2] = f2tf(reg[i].z); p[3] = f2tf(reg[i].w);
    }
}
__device__ __forceinline__ void mma_chunk_kn(const uint32_t* smA, const uint32_t* smB,
                                             float acc[2][4][4],
                                             int warp_m, int warp_n, int lr, int lc)
{
    #pragma unroll
    for (int ks = 0; ks < 4; ks++) {
        int kb = ks*8, kb4 = ks*2;
        int swz = ((kb4 ^ lr) << 2) + lc;
        uint32_t b[4][2];
        #pragma unroll
        for (int j = 0; j < 4; j++) {
            int n = warp_n + j*8 + lr;
            b[j][0] = smB[(kb + lc)*BSTRIDE + n];
            b[j][1] = smB[(kb + 4 + lc)*BSTRIDE + n];
        }
        #pragma unroll
        for (int i = 0; i < 2; i++) {
            int mb = warp_m + i*16;
            uint32_t a0 = smA[(mb + lr)*32 + swz];
            uint32_t a1 = smA[(mb + 8 + lr)*32 + swz];
            uint32_t a2 = smA[(mb + lr)*32 + (swz ^ 4)];
            uint32_t a3 = smA[(mb + 8 + lr)*32 + (swz ^ 4)];
            #pragma unroll
            for (int j = 0; j < 4; j++)
                mma_tf32(acc[i][j], a0, a1, a2, a3, b[j][0], b[j][1]);
        }
    }
}

// O = attn @ V -> half output
__global__ __launch_bounds__(256)
void av_tc(const float* __restrict__ attn, const float* __restrict__ V,
           __half* __restrict__ O)
{
    int zb = blockIdx.z, b = zb >> 3, h = zb & 7;
    int m0 = blockIdx.y * TMM;
    int t = threadIdx.x, wid = t >> 5, lane = t & 31;
    int lr = lane >> 2, lc = lane & 3;
    int warp_m = (wid & 1)*32, warp_n = (wid >> 1)*32;

    const float* A  = attn + (size_t)zb*TT*TT + (size_t)m0*TT;
    const float* Bv = V + (size_t)b*TT*CC + h*HD;
    __half*      Co = O + (size_t)b*TT*CC + h*HD;

    __shared__ uint32_t smA[TMM*32];
    __shared__ uint32_t smB[KC*BSTRIDE];

    float acc[2][4][4] = {};
    float4 rA[2], rB[4];
    int nch = (m0 + TMM)/KC;

    ldg_rs<TMM,false>(rA, A, TT, 0, TT);
    ldg_kn<false,false>(rB, Bv, CC, 0, 0, HD, TT);

    for (int c = 0; c < nch; c++) {
        sts_rs<TMM>(smA, rA);
        sts_kn(smB, rB);
        __syncthreads();
        if (c + 1 < nch) {
            ldg_rs<TMM,false>(rA, A, TT, (c+1)*KC, TT);
            ldg_kn<false,false>(rB, Bv, CC, (c+1)*KC, 0, HD, TT);
        }
        mma_chunk_kn(smA, smB, acc, warp_m, warp_n, lr, lc);
        __syncthreads();
    }

    #pragma unroll
    for (int i = 0; i < 2; i++) {
        int r0 = m0 + warp_m + i*16 + lr;
        #pragma unroll
        for (int j = 0; j < 4; j++) {
            int cg = warp_n + j*8 + 2*lc;
            *(__half2*)&Co[(size_t)r0*CC + cg]     = __floats2half2_rn(acc[i][j][0], acc[i][j][1]);
            *(__half2*)&Co[(size_t)(r0+8)*CC + cg] = __floats2half2_rn(acc[i][j][2], acc[i][j][3]);
        }
    }
}

// ---------------- embedding / layernorm ----------------
__global__ void embed_kernel(const int* __restrict__ x, const float* __restrict__ emb,
                             float* __restrict__ h)
{
    int idx = blockIdx.x * 256 + threadIdx.x;
    int n = idx >> 8, c = idx & 255;
    ((float4*)h)[idx] = ((const float4*)emb)[(size_t)x[n]*(CC/4) + c];
}

__global__ void ln_kernel(const float* __restrict__ in, const float* __restrict__ g,
                          const float* __restrict__ b, __half* __restrict__ out)
{
    int row = blockIdx.x, tid = threadIdx.x;
    const float4* xr = (const float4*)(in + (size_t)row*CC);
    float4 x = xr[tid];
    __shared__ float red[32];

    float s = x.x + x.y + x.z + x.w;
    #pragma unroll
    for (int o = 16; o; o >>= 1) s += __shfl_xor_sync(0xffffffffu, s, o);
    if ((tid & 31) == 0) red[tid >> 5] = s;
    __syncthreads();
    if (tid == 0) {
        float tsum = 0.f;
        #pragma unroll
        for (int w = 0; w < 8; w++) tsum += red[w];
        red[0] = tsum;
    }
    __syncthreads();
    float mu = red[0] * (1.f/CC);
    __syncthreads();

    float4 d = make_float4(x.x-mu, x.y-mu, x.z-mu, x.w-mu);
    float v = d.x*d.x + d.y*d.y + d.z*d.z + d.w*d.w;
    #pragma unroll
    for (int o = 16; o; o >>= 1) v += __shfl_xor_sync(0xffffffffu, v, o);
    if ((tid & 31) == 0) red[tid >> 5] = v;
    __syncthreads();
    if (tid == 0) {
        float tsum = 0.f;
        #pragma unroll
        for (int w = 0; w < 8; w++) tsum += red[w];
        red[0] = tsum;
    }
    __syncthreads();
    float rstd = rsqrtf(red[0] * (1.f/CC) + LN_EPS);

    float4 gg = ((const float4*)g)[tid];
    float4 bb = ((const float4*)b)[tid];
    __half2 h0 = __floats2half2_rn(d.x*rstd*gg.x + bb.x, d.y*rstd*gg.y + bb.y);
    __half2 h1 = __floats2half2_rn(d.z*rstd*gg.z + bb.z, d.w*rstd*gg.w + bb.w);
    uint2 pk; pk.x = *(uint32_t*)&h0; pk.y = *(uint32_t*)&h1;
    *(uint2*)&out[(size_t)row*CC + tid*4] = pk;
}

// ---------------- host ----------------
extern "C" void kernel_launch(void* const* d_in, const int* in_sizes, int n_in,
                              void* d_out, int out_size)
{
    const int*   x    = (const int*)  d_in[0];
    const float* emb  = (const float*)d_in[1];
    const float* Wq   = (const float*)d_in[2];
    const float* bq   = (const float*)d_in[3];
    const float* Wk   = (const float*)d_in[4];
    const float* bk   = (const float*)d_in[5];
    const float* Wv   = (const float*)d_in[6];
    const float* bv   = (const float*)d_in[7];
    const float* Wo   = (const float*)d_in[8];
    const float* bo   = (const float*)d_in[9];
    const float* W1   = (const float*)d_in[10];
    const float* b1   = (const float*)d_in[11];
    const float* W2   = (const float*)d_in[12];
    const float* b2   = (const float*)d_in[13];
    const float* ln1g = (const float*)d_in[14];
    const float* ln1b = (const float*)d_in[15];
    const float* ln3g = (const float*)d_in[16];
    const float* ln3b = (const float*)d_in[17];
    const float* lnfg = (const float*)d_in[18];
    const float* lnfb = (const float*)d_in[19];
    const float* Wout = (const float*)d_in[20];
    const float* bout = (const float*)d_in[21];

    float* out_logits = (float*)d_out;
    float* out_attn   = out_logits + (size_t)BB*TT*VV;

    float *h, *v;
    __half *q_h, *k_h, *hn_h, *o_h, *ff_h, *wtq, *wtk, *wtv, *wto, *wt1, *wt2, *wtout;
    cudaGetSymbolAddress((void**)&h,    g_h);
    cudaGetSymbolAddress((void**)&v,    g_v);
    cudaGetSymbolAddress((void**)&q_h,  g_q_h);
    cudaGetSymbolAddress((void**)&k_h,  g_k_h);
    cudaGetSymbolAddress((void**)&hn_h, g_hn_h);
    cudaGetSymbolAddress((void**)&o_h,  g_o_h);
    cudaGetSymbolAddress((void**)&ff_h, g_ff_h);
    cudaGetSymbolAddress((void**)&wtq,  g_wtq);
    cudaGetSymbolAddress((void**)&wtk,  g_wtk);
    cudaGetSymbolAddress((void**)&wtv,  g_wtv);
    cudaGetSymbolAddress((void**)&wto,  g_wto);
    cudaGetSymbolAddress((void**)&wt1,  g_wt1);
    cudaGetSymbolAddress((void**)&wt2,  g_wt2);
    cudaGetSymbolAddress((void**)&wtout,g_wtout);

    cudaFuncSetAttribute(scores_h, cudaFuncAttributeMaxDynamicSharedMemorySize, SCORES_SMEM);

    dim3 tt(256);
    transpose_h<<<dim3(CC/64, CC/64, LL), tt>>>(Wq, wtq, CC, CC, CC, (size_t)CC*CC, (size_t)CC*CC);
    transpose_h<<<dim3(CC/64, CC/64, LL), tt>>>(Wk, wtk, CC, CC, CC, (size_t)CC*CC, (size_t)CC*CC);
    transpose_h<<<dim3(CC/64, CC/64, LL), tt>>>(Wv, wtv, CC, CC, CC, (size_t)CC*CC, (size_t)CC*CC);
    transpose_h<<<dim3(CC/64, CC/64, LL), tt>>>(Wo, wto, CC, CC, CC, (size_t)CC*CC, (size_t)CC*CC);
    transpose_h<<<dim3(2, CC/64, LL), tt>>>(W1, wt1, CC, FFD, CC, (size_t)CC*FFD, (size_t)FFD*CC);
    transpose_h<<<dim3(CC/64, 2, LL), tt>>>(W2, wt2, FFD, CC, FFP, (size_t)FFD*CC, (size_t)CC*FFP);
    transpose_h<<<dim3(VV/64, CC/64, 1), tt>>>(Wout, wtout, CC, VV, CC, 0, 0);

    embed_kernel<<<NTOK, 256>>>(x, emb, h);

    dim3 thr(256);
    dim3 gC(NTOK/GT, CC/GT);
    dim3 gS(TT/TNN, TT/TMM, BB*HH);
    dim3 gAV(1, TT/TMM, BB*HH);
    dim3 gF1(NTOK/GT, 1);
    dim3 gL(NTOK/GT, VV/GT);

    for (int l = 0; l < LL; l++) {
        float* attnL = out_attn + (size_t)l*BB*HH*TT*TT;

        ln_kernel<<<NTOK, 256>>>(h, ln1g + l*CC, ln1b + l*CC, hn_h);

        gemm_hh<false,false,true><<<gC, thr>>>(hn_h, CC, wtq + (size_t)l*CC*CC, CC,
                                               bq + l*CC, nullptr, 0, nullptr, q_h, CC, CC, CC);
        gemm_hh<false,false,true><<<gC, thr>>>(hn_h, CC, wtk + (size_t)l*CC*CC, CC,
                                               bk + l*CC, nullptr, 0, nullptr, k_h, CC, CC, CC);
        gemm_hh<false,false,false><<<gC, thr>>>(hn_h, CC, wtv + (size_t)l*CC*CC, CC,
                                                bv + l*CC, nullptr, 0, v, nullptr, CC, CC, CC);

        scores_h<<<gS, thr, SCORES_SMEM>>>(q_h, k_h, attnL);
        softmax_kernel<<<BB*HH*TT, 256>>>(attnL);
        av_tc<<<gAV, thr>>>(attnL, v, o_h);

        gemm_hh<false,true,false><<<gC, thr>>>(o_h, CC, wto + (size_t)l*CC*CC, CC,
                                               bo + l*CC, h, CC, h, nullptr, CC, CC, CC);

        ln_kernel<<<NTOK, 256>>>(h, ln3g + l*CC, ln3b + l*CC, hn_h);

        gemm_hh<true,false,true><<<gF1, thr>>>(hn_h, CC, wt1 + (size_t)l*FFD*CC, CC,
                                               b1 + l*FFD, nullptr, 0, nullptr, ff_h, FFP, FFD, CC);
        gemm_hh<false,true,false><<<gC, thr>>>(ff_h, FFP, wt2 + (size_t)l*CC*FFP, FFP,
                                               b2 + l*CC, h, CC, h, nullptr, CC, CC, FFP);
    }

    ln_kernel<<<NTOK, 256>>>(h, lnfg, lnfb, hn_h);
    gemm_hh<false,false,false><<<gL, thr>>>(hn_h, CC, wtout, CC,
                                            bout, nullptr, 0, out_logits, nullptr, VV, VV, CC);
}